// round 4
// baseline (speedup 1.0000x reference)
#include <cuda_runtime.h>
#include <math.h>

#define NPTS 100000
#define CH   128
#define KN   16
#define BP   16
#define NBLK_RED 256

// ---------------- scratch (device globals; no allocations allowed) ----------
__device__ float        g_x  [(size_t)NPTS * CH];   // LayerNorm output
__device__ float        g_mf [(size_t)NPTS * CH];   // neighbor mean feature
__device__ float        g_bnd[NPTS];                // boundary score
__device__ float        g_part[NBLK_RED * 3];       // partial sums of points
__device__ float        g_sum3[3];                  // total sum of points
__device__ unsigned int g_max3[3];                  // max |p - mean| as uint bits

__device__ __forceinline__ float gelu_exact(float v) {
    return 0.5f * v * (1.0f + erff(v * 0.70710678118654752f));
}
__device__ __forceinline__ float sigm(float v) {
    return 1.0f / (1.0f + __expf(-v));
}

// ---------------- K0: reset accumulators (graph replays re-run this) --------
__global__ void k_reset() {
    if (threadIdx.x < 3) { g_sum3[threadIdx.x] = 0.0f; g_max3[threadIdx.x] = 0u; }
}

// ---------------- K1: per-block partial sums of points ----------------------
__global__ void k_psum(const float* __restrict__ pts) {
    float s0 = 0.f, s1 = 0.f, s2 = 0.f;
    for (int i = blockIdx.x * blockDim.x + threadIdx.x; i < NPTS;
         i += gridDim.x * blockDim.x) {
        s0 += pts[3 * i + 0];
        s1 += pts[3 * i + 1];
        s2 += pts[3 * i + 2];
    }
    __shared__ float sh[8][3];
    #pragma unroll
    for (int o = 16; o > 0; o >>= 1) {
        s0 += __shfl_xor_sync(0xffffffffu, s0, o);
        s1 += __shfl_xor_sync(0xffffffffu, s1, o);
        s2 += __shfl_xor_sync(0xffffffffu, s2, o);
    }
    int w = threadIdx.x >> 5, l = threadIdx.x & 31;
    if (l == 0) { sh[w][0] = s0; sh[w][1] = s1; sh[w][2] = s2; }
    __syncthreads();
    if (threadIdx.x == 0) {
        float t0 = 0.f, t1 = 0.f, t2 = 0.f;
        #pragma unroll
        for (int i = 0; i < 8; i++) { t0 += sh[i][0]; t1 += sh[i][1]; t2 += sh[i][2]; }
        g_part[blockIdx.x * 3 + 0] = t0;
        g_part[blockIdx.x * 3 + 1] = t1;
        g_part[blockIdx.x * 3 + 2] = t2;
    }
}

// ---------------- K2: combine partials (deterministic) ----------------------
__global__ void k_psum2() {
    float s0 = g_part[threadIdx.x * 3 + 0];
    float s1 = g_part[threadIdx.x * 3 + 1];
    float s2 = g_part[threadIdx.x * 3 + 2];
    __shared__ float sh[8][3];
    #pragma unroll
    for (int o = 16; o > 0; o >>= 1) {
        s0 += __shfl_xor_sync(0xffffffffu, s0, o);
        s1 += __shfl_xor_sync(0xffffffffu, s1, o);
        s2 += __shfl_xor_sync(0xffffffffu, s2, o);
    }
    int w = threadIdx.x >> 5, l = threadIdx.x & 31;
    if (l == 0) { sh[w][0] = s0; sh[w][1] = s1; sh[w][2] = s2; }
    __syncthreads();
    if (threadIdx.x == 0) {
        float t0 = 0.f, t1 = 0.f, t2 = 0.f;
        #pragma unroll
        for (int i = 0; i < 8; i++) { t0 += sh[i][0]; t1 += sh[i][1]; t2 += sh[i][2]; }
        g_sum3[0] = t0; g_sum3[1] = t1; g_sum3[2] = t2;
    }
}

// ---------------- K3: max |p - mean| per dim (atomicMax on uint bits) -------
__global__ void k_max(const float* __restrict__ pts) {
    float m0 = g_sum3[0] * (1.0f / NPTS);
    float m1 = g_sum3[1] * (1.0f / NPTS);
    float m2 = g_sum3[2] * (1.0f / NPTS);
    float a0 = 0.f, a1 = 0.f, a2 = 0.f;
    for (int i = blockIdx.x * blockDim.x + threadIdx.x; i < NPTS;
         i += gridDim.x * blockDim.x) {
        a0 = fmaxf(a0, fabsf(pts[3 * i + 0] - m0));
        a1 = fmaxf(a1, fabsf(pts[3 * i + 1] - m1));
        a2 = fmaxf(a2, fabsf(pts[3 * i + 2] - m2));
    }
    #pragma unroll
    for (int o = 16; o > 0; o >>= 1) {
        a0 = fmaxf(a0, __shfl_xor_sync(0xffffffffu, a0, o));
        a1 = fmaxf(a1, __shfl_xor_sync(0xffffffffu, a1, o));
        a2 = fmaxf(a2, __shfl_xor_sync(0xffffffffu, a2, o));
    }
    __shared__ float sh[8][3];
    int w = threadIdx.x >> 5, l = threadIdx.x & 31;
    if (l == 0) { sh[w][0] = a0; sh[w][1] = a1; sh[w][2] = a2; }
    __syncthreads();
    if (threadIdx.x == 0) {
        float t0 = 0.f, t1 = 0.f, t2 = 0.f;
        #pragma unroll
        for (int i = 0; i < 8; i++) {
            t0 = fmaxf(t0, sh[i][0]); t1 = fmaxf(t1, sh[i][1]); t2 = fmaxf(t2, sh[i][2]);
        }
        atomicMax(&g_max3[0], __float_as_uint(t0));
        atomicMax(&g_max3[1], __float_as_uint(t1));
        atomicMax(&g_max3[2], __float_as_uint(t2));
    }
}

// ---------------- K4: LayerNorm, warp per row, float4 -----------------------
__global__ void k_ln(const float* __restrict__ feats,
                     const float* __restrict__ gg, const float* __restrict__ bb) {
    int row = blockIdx.x * 8 + (threadIdx.x >> 5);
    if (row >= NPTS) return;
    int l = threadIdx.x & 31;
    float4 v = reinterpret_cast<const float4*>(feats + (size_t)row * CH)[l];
    float s = v.x + v.y + v.z + v.w;
    #pragma unroll
    for (int o = 16; o > 0; o >>= 1) s += __shfl_xor_sync(0xffffffffu, s, o);
    float mean = s * (1.0f / CH);
    float dx = v.x - mean, dy = v.y - mean, dz = v.z - mean, dw = v.w - mean;
    float q = dx * dx + dy * dy + dz * dz + dw * dw;
    #pragma unroll
    for (int o = 16; o > 0; o >>= 1) q += __shfl_xor_sync(0xffffffffu, q, o);
    float rstd = rsqrtf(q * (1.0f / CH) + 1e-5f);
    float4 g4 = reinterpret_cast<const float4*>(gg)[l];
    float4 b4 = reinterpret_cast<const float4*>(bb)[l];
    float4 o4;
    o4.x = dx * rstd * g4.x + b4.x;
    o4.y = dy * rstd * g4.y + b4.y;
    o4.z = dz * rstd * g4.z + b4.z;
    o4.w = dw * rstd * g4.w + b4.w;
    reinterpret_cast<float4*>(g_x + (size_t)row * CH)[l] = o4;
}

// ---------------- K5: neighbor gather + mean + diffs + boundary MLP ---------
// NOTE: neighbors arrive as int32 (harness downcasts int64 -> int32).
__global__ void k_gather(const float* __restrict__ pts,
                         const int* __restrict__ nbr,
                         const float* __restrict__ bw1, const float* __restrict__ bb1,
                         const float* __restrict__ bw2, const float* __restrict__ bb2) {
    int n = blockIdx.x;
    int t = threadIdx.x;  // 128 threads
    __shared__ int   sidx[KN];
    __shared__ float sval[KN];
    __shared__ float sc[3];
    __shared__ float sred[4];
    __shared__ float stot;

    if (t < KN) {
        int v = nbr[(size_t)n * KN + t];
        sval[t] = (v >= 0 && v < NPTS) ? 1.0f : 0.0f;
        int c = v < 0 ? 0 : (v >= NPTS ? (NPTS - 1) : v);
        sidx[t] = c;
    }
    __syncthreads();

    float denom = 0.f;
    #pragma unroll
    for (int k = 0; k < KN; k++) denom += sval[k];
    denom = fmaxf(denom, 1.0f);
    float inv = 1.0f / denom;

    float acc = 0.f;
    #pragma unroll
    for (int k = 0; k < KN; k++)
        acc += sval[k] * g_x[(size_t)sidx[k] * CH + t];
    float mf = acc * inv;
    g_mf[(size_t)n * CH + t] = mf;

    float xd = g_x[(size_t)n * CH + t] - mf;

    // block sum of xd*xd
    float v0 = xd * xd;
    #pragma unroll
    for (int o = 16; o > 0; o >>= 1) v0 += __shfl_xor_sync(0xffffffffu, v0, o);
    if ((t & 31) == 0) sred[t >> 5] = v0;
    __syncthreads();
    if (t == 0) stot = sred[0] + sred[1] + sred[2] + sred[3];

    if (t < 3) {
        float a = 0.f;
        #pragma unroll
        for (int k = 0; k < KN; k++)
            a += sval[k] * pts[(size_t)sidx[k] * 3 + t];
        float mp = a * inv;
        float d = pts[(size_t)n * 3 + t] - mp;
        sc[t] = d * d;
    }
    __syncthreads();

    float fd = sqrtf(stot);
    float cd = sqrtf(sc[0] + sc[1] + sc[2]);

    float h = gelu_exact(fd * bw1[t] + cd * bw1[CH + t] + bb1[t]);
    float v1 = h * bw2[t];
    __syncthreads();  // protect sred reuse
    #pragma unroll
    for (int o = 16; o > 0; o >>= 1) v1 += __shfl_xor_sync(0xffffffffu, v1, o);
    if ((t & 31) == 0) sred[t >> 5] = v1;
    __syncthreads();
    if (t == 0) g_bnd[n] = sigm(sred[0] + sred[1] + sred[2] + sred[3] + bb2[0]);
}

// ---------------- shared-input matvec accumulation --------------------------
// acc[p] += sum_i in[p][i] * w[i*CH + j]   (thread owns output j; float4 LDS)
__device__ __forceinline__ void accum128(float acc[BP],
                                         const float (&in)[BP][CH],
                                         const float* __restrict__ w, int j) {
    for (int i = 0; i < CH; i += 4) {
        float w0 = w[(i + 0) * CH + j];
        float w1 = w[(i + 1) * CH + j];
        float w2 = w[(i + 2) * CH + j];
        float w3 = w[(i + 3) * CH + j];
        #pragma unroll
        for (int p = 0; p < BP; p++) {
            float4 v = *reinterpret_cast<const float4*>(&in[p][i]);
            acc[p] = fmaf(v.x, w0, acc[p]);
            acc[p] = fmaf(v.y, w1, acc[p]);
            acc[p] = fmaf(v.z, w2, acc[p]);
            acc[p] = fmaf(v.w, w3, acc[p]);
        }
    }
}

// ---------------- K6: fused MLPs, BP points per block ------------------------
__global__ __launch_bounds__(128)
void k_mlp(const float* __restrict__ pts, const float* __restrict__ feats,
           const float* __restrict__ cpw1, const float* __restrict__ cpb1,
           const float* __restrict__ cpw2, const float* __restrict__ cpb2,
           const float* __restrict__ mw1,  const float* __restrict__ mb1,
           const float* __restrict__ mw2,  const float* __restrict__ mb2,
           const float* __restrict__ gw1,  const float* __restrict__ gb1,
           const float* __restrict__ gw2,  const float* __restrict__ gb2,
           const float* __restrict__ ow,   const float* __restrict__ ob,
           float* __restrict__ out) {
    __shared__ float xs[BP][CH];   // x
    __shared__ float ms[BP][CH];   // mean_feat
    __shared__ float cs[BP][CH];   // coord_embed
    __shared__ float hs[BP][CH];   // hidden scratch
    __shared__ float rs[BP][CH];   // refined / gate*refined
    __shared__ float bnd[BP];
    __shared__ float cpt[BP][3];

    int t = threadIdx.x;
    int p0 = blockIdx.x * BP;

    #pragma unroll
    for (int p = 0; p < BP; p++) {
        xs[p][t] = g_x [(size_t)(p0 + p) * CH + t];
        ms[p][t] = g_mf[(size_t)(p0 + p) * CH + t];
    }
    if (t < BP) bnd[t] = g_bnd[p0 + t];
    if (t < BP * 3) {
        int p = t / 3, d = t - 3 * p;
        float mean = g_sum3[d] * (1.0f / NPTS);
        float scl  = fmaxf(__uint_as_float(g_max3[d]), 1e-6f);
        cpt[p][d] = (pts[(size_t)(p0 + p) * 3 + d] - mean) / scl;
    }
    __syncthreads();

    // coord-embed hidden (3 -> 128)
    {
        float w0 = cpw1[t], w1 = cpw1[CH + t], w2 = cpw1[2 * CH + t], b = cpb1[t];
        #pragma unroll
        for (int p = 0; p < BP; p++)
            hs[p][t] = gelu_exact(cpt[p][0] * w0 + cpt[p][1] * w1 + cpt[p][2] * w2 + b);
    }
    __syncthreads();

    // coord_embed = hs @ cp_w2 + b
    {
        float acc[BP]; float b = cpb2[t];
        #pragma unroll
        for (int p = 0; p < BP; p++) acc[p] = b;
        accum128(acc, hs, cpw2, t);
        #pragma unroll
        for (int p = 0; p < BP; p++) cs[p][t] = acc[p];
        __syncthreads();
    }

    // mix hidden: [x(128), mf(128), boundary(1), ce(128)] @ mix_w1 -> gelu
    {
        float acc[BP];
        float b = mb1[t];
        float wb = mw1[256 * CH + t];
        #pragma unroll
        for (int p = 0; p < BP; p++) acc[p] = b + bnd[p] * wb;
        accum128(acc, xs, mw1, t);
        accum128(acc, ms, mw1 + 128 * CH, t);
        accum128(acc, cs, mw1 + 257 * CH, t);
        #pragma unroll
        for (int p = 0; p < BP; p++) hs[p][t] = gelu_exact(acc[p]);
        __syncthreads();
    }

    // refined = hs @ mix_w2 + b
    {
        float acc[BP]; float b = mb2[t];
        #pragma unroll
        for (int p = 0; p < BP; p++) acc[p] = b;
        accum128(acc, hs, mw2, t);
        #pragma unroll
        for (int p = 0; p < BP; p++) rs[p][t] = acc[p];
        __syncthreads();
    }

    // gate hidden: [x, mf, boundary] @ gate_w1 -> gelu
    {
        float acc[BP];
        float b = gb1[t];
        float wb = gw1[256 * CH + t];
        #pragma unroll
        for (int p = 0; p < BP; p++) acc[p] = b + bnd[p] * wb;
        accum128(acc, xs, gw1, t);
        accum128(acc, ms, gw1 + 128 * CH, t);
        #pragma unroll
        for (int p = 0; p < BP; p++) hs[p][t] = gelu_exact(acc[p]);
        __syncthreads();
    }

    // gate = sigmoid(hs @ gate_w2 + b); rs *= gate
    {
        float acc[BP]; float b = gb2[t];
        #pragma unroll
        for (int p = 0; p < BP; p++) acc[p] = b;
        accum128(acc, hs, gw2, t);
        #pragma unroll
        for (int p = 0; p < BP; p++) rs[p][t] = sigm(acc[p]) * rs[p][t];
        __syncthreads();
    }

    // out = feats + rs @ out_w + b
    {
        float acc[BP]; float b = ob[t];
        #pragma unroll
        for (int p = 0; p < BP; p++) acc[p] = b;
        accum128(acc, rs, ow, t);
        #pragma unroll
        for (int p = 0; p < BP; p++)
            out[(size_t)(p0 + p) * CH + t] =
                feats[(size_t)(p0 + p) * CH + t] + acc[p];
    }
}

// ---------------- launch -----------------------------------------------------
extern "C" void kernel_launch(void* const* d_in, const int* in_sizes, int n_in,
                              void* d_out, int out_size) {
    const float* feats = (const float*)d_in[0];
    const float* pts   = (const float*)d_in[1];
    const int*   nbr   = (const int*)d_in[2];     // int64 downcast to int32 by harness
    const float* ln_g  = (const float*)d_in[3];
    const float* ln_b  = (const float*)d_in[4];
    const float* cpw1  = (const float*)d_in[5];
    const float* cpb1  = (const float*)d_in[6];
    const float* cpw2  = (const float*)d_in[7];
    const float* cpb2  = (const float*)d_in[8];
    const float* bw1   = (const float*)d_in[9];
    const float* bb1   = (const float*)d_in[10];
    const float* bw2   = (const float*)d_in[11];
    const float* bb2   = (const float*)d_in[12];
    const float* mw1   = (const float*)d_in[13];
    const float* mb1   = (const float*)d_in[14];
    const float* mw2   = (const float*)d_in[15];
    const float* mb2   = (const float*)d_in[16];
    const float* gw1   = (const float*)d_in[17];
    const float* gb1   = (const float*)d_in[18];
    const float* gw2   = (const float*)d_in[19];
    const float* gb2   = (const float*)d_in[20];
    const float* ow    = (const float*)d_in[21];
    const float* ob    = (const float*)d_in[22];
    float* out = (float*)d_out;

    (void)ln_g; (void)ln_b; (void)in_sizes; (void)n_in; (void)out_size;

    k_reset<<<1, 32>>>();
    k_psum<<<NBLK_RED, 256>>>(pts);
    k_psum2<<<1, NBLK_RED>>>();
    k_max<<<NBLK_RED, 256>>>(pts);
    k_ln<<<(NPTS + 7) / 8, 256>>>(feats, ln_g, ln_b);
    k_gather<<<NPTS, 128>>>(pts, nbr, bw1, bb1, bw2, bb2);
    k_mlp<<<NPTS / BP, 128>>>(pts, feats,
                              cpw1, cpb1, cpw2, cpb2,
                              mw1, mb1, mw2, mb2,
                              gw1, gb1, gw2, gb2,
                              ow, ob, out);
}

// round 5
// speedup vs baseline: 3.1216x; 3.1216x over previous
#include <cuda_runtime.h>
#include <cuda_bf16.h>
#include <math.h>
#include <stdint.h>

#define NPTS 100000
#define CH   128
#define KN   16
#define BP   32              // points per k_mlp block (two m16 tiles)
#define NBLK_RED 256

// ---------------- scratch (device globals; no allocations allowed) ----------
__device__ float        g_x  [(size_t)NPTS * CH];   // LayerNorm output
__device__ float        g_mf [(size_t)NPTS * CH];   // neighbor mean feature
__device__ float        g_bnd[NPTS];                // boundary score
__device__ float        g_part[NBLK_RED * 3];
__device__ float        g_sum3[3];
__device__ unsigned int g_max3[3];
__device__ uint2        g_pk[9 * 4096];             // fragment-packed bf16 weights (288KB)

__device__ __forceinline__ float gelu_exact(float v) {
    return 0.5f * v * (1.0f + erff(v * 0.70710678118654752f));
}
__device__ __forceinline__ float sigm(float v) {
    return 1.0f / (1.0f + __expf(-v));
}

// ---------------- K0: reset accumulators ------------------------------------
__global__ void k_reset() {
    if (threadIdx.x < 3) { g_sum3[threadIdx.x] = 0.0f; g_max3[threadIdx.x] = 0u; }
}

// ---------------- K1: per-block partial sums of points ----------------------
__global__ void k_psum(const float* __restrict__ pts) {
    float s0 = 0.f, s1 = 0.f, s2 = 0.f;
    for (int i = blockIdx.x * blockDim.x + threadIdx.x; i < NPTS;
         i += gridDim.x * blockDim.x) {
        s0 += pts[3 * i + 0];
        s1 += pts[3 * i + 1];
        s2 += pts[3 * i + 2];
    }
    __shared__ float sh[8][3];
    #pragma unroll
    for (int o = 16; o > 0; o >>= 1) {
        s0 += __shfl_xor_sync(0xffffffffu, s0, o);
        s1 += __shfl_xor_sync(0xffffffffu, s1, o);
        s2 += __shfl_xor_sync(0xffffffffu, s2, o);
    }
    int w = threadIdx.x >> 5, l = threadIdx.x & 31;
    if (l == 0) { sh[w][0] = s0; sh[w][1] = s1; sh[w][2] = s2; }
    __syncthreads();
    if (threadIdx.x == 0) {
        float t0 = 0.f, t1 = 0.f, t2 = 0.f;
        #pragma unroll
        for (int i = 0; i < 8; i++) { t0 += sh[i][0]; t1 += sh[i][1]; t2 += sh[i][2]; }
        g_part[blockIdx.x * 3 + 0] = t0;
        g_part[blockIdx.x * 3 + 1] = t1;
        g_part[blockIdx.x * 3 + 2] = t2;
    }
}

// ---------------- K2: combine partials --------------------------------------
__global__ void k_psum2() {
    float s0 = g_part[threadIdx.x * 3 + 0];
    float s1 = g_part[threadIdx.x * 3 + 1];
    float s2 = g_part[threadIdx.x * 3 + 2];
    __shared__ float sh[8][3];
    #pragma unroll
    for (int o = 16; o > 0; o >>= 1) {
        s0 += __shfl_xor_sync(0xffffffffu, s0, o);
        s1 += __shfl_xor_sync(0xffffffffu, s1, o);
        s2 += __shfl_xor_sync(0xffffffffu, s2, o);
    }
    int w = threadIdx.x >> 5, l = threadIdx.x & 31;
    if (l == 0) { sh[w][0] = s0; sh[w][1] = s1; sh[w][2] = s2; }
    __syncthreads();
    if (threadIdx.x == 0) {
        float t0 = 0.f, t1 = 0.f, t2 = 0.f;
        #pragma unroll
        for (int i = 0; i < 8; i++) { t0 += sh[i][0]; t1 += sh[i][1]; t2 += sh[i][2]; }
        g_sum3[0] = t0; g_sum3[1] = t1; g_sum3[2] = t2;
    }
}

// ---------------- K3: max |p - mean| per dim --------------------------------
__global__ void k_max(const float* __restrict__ pts) {
    float m0 = g_sum3[0] * (1.0f / NPTS);
    float m1 = g_sum3[1] * (1.0f / NPTS);
    float m2 = g_sum3[2] * (1.0f / NPTS);
    float a0 = 0.f, a1 = 0.f, a2 = 0.f;
    for (int i = blockIdx.x * blockDim.x + threadIdx.x; i < NPTS;
         i += gridDim.x * blockDim.x) {
        a0 = fmaxf(a0, fabsf(pts[3 * i + 0] - m0));
        a1 = fmaxf(a1, fabsf(pts[3 * i + 1] - m1));
        a2 = fmaxf(a2, fabsf(pts[3 * i + 2] - m2));
    }
    #pragma unroll
    for (int o = 16; o > 0; o >>= 1) {
        a0 = fmaxf(a0, __shfl_xor_sync(0xffffffffu, a0, o));
        a1 = fmaxf(a1, __shfl_xor_sync(0xffffffffu, a1, o));
        a2 = fmaxf(a2, __shfl_xor_sync(0xffffffffu, a2, o));
    }
    __shared__ float sh[8][3];
    int w = threadIdx.x >> 5, l = threadIdx.x & 31;
    if (l == 0) { sh[w][0] = a0; sh[w][1] = a1; sh[w][2] = a2; }
    __syncthreads();
    if (threadIdx.x == 0) {
        float t0 = 0.f, t1 = 0.f, t2 = 0.f;
        #pragma unroll
        for (int i = 0; i < 8; i++) {
            t0 = fmaxf(t0, sh[i][0]); t1 = fmaxf(t1, sh[i][1]); t2 = fmaxf(t2, sh[i][2]);
        }
        atomicMax(&g_max3[0], __float_as_uint(t0));
        atomicMax(&g_max3[1], __float_as_uint(t1));
        atomicMax(&g_max3[2], __float_as_uint(t2));
    }
}

// ---------------- K4: LayerNorm, warp per row, float4 -----------------------
__global__ void k_ln(const float* __restrict__ feats,
                     const float* __restrict__ gg, const float* __restrict__ bb) {
    int row = blockIdx.x * 8 + (threadIdx.x >> 5);
    if (row >= NPTS) return;
    int l = threadIdx.x & 31;
    float4 v = reinterpret_cast<const float4*>(feats + (size_t)row * CH)[l];
    float s = v.x + v.y + v.z + v.w;
    #pragma unroll
    for (int o = 16; o > 0; o >>= 1) s += __shfl_xor_sync(0xffffffffu, s, o);
    float mean = s * (1.0f / CH);
    float dx = v.x - mean, dy = v.y - mean, dz = v.z - mean, dw = v.w - mean;
    float q = dx * dx + dy * dy + dz * dz + dw * dw;
    #pragma unroll
    for (int o = 16; o > 0; o >>= 1) q += __shfl_xor_sync(0xffffffffu, q, o);
    float rstd = rsqrtf(q * (1.0f / CH) + 1e-5f);
    float4 g4 = reinterpret_cast<const float4*>(gg)[l];
    float4 b4 = reinterpret_cast<const float4*>(bb)[l];
    float4 o4;
    o4.x = dx * rstd * g4.x + b4.x;
    o4.y = dy * rstd * g4.y + b4.y;
    o4.z = dz * rstd * g4.z + b4.z;
    o4.w = dw * rstd * g4.w + b4.w;
    reinterpret_cast<float4*>(g_x + (size_t)row * CH)[l] = o4;
}

// ---------------- K5: neighbor gather + mean + diffs + boundary MLP ---------
__global__ void k_gather(const float* __restrict__ pts,
                         const int* __restrict__ nbr,
                         const float* __restrict__ bw1, const float* __restrict__ bb1,
                         const float* __restrict__ bw2, const float* __restrict__ bb2) {
    int n = blockIdx.x;
    int t = threadIdx.x;  // 128 threads
    __shared__ int   sidx[KN];
    __shared__ float sval[KN];
    __shared__ float sc[3];
    __shared__ float sred[4];
    __shared__ float stot;

    if (t < KN) {
        int v = nbr[(size_t)n * KN + t];
        sval[t] = (v >= 0 && v < NPTS) ? 1.0f : 0.0f;
        int c = v < 0 ? 0 : (v >= NPTS ? (NPTS - 1) : v);
        sidx[t] = c;
    }
    __syncthreads();

    float denom = 0.f;
    #pragma unroll
    for (int k = 0; k < KN; k++) denom += sval[k];
    denom = fmaxf(denom, 1.0f);
    float inv = 1.0f / denom;

    float acc = 0.f;
    #pragma unroll
    for (int k = 0; k < KN; k++)
        acc += sval[k] * g_x[(size_t)sidx[k] * CH + t];
    float mf = acc * inv;
    g_mf[(size_t)n * CH + t] = mf;

    float xd = g_x[(size_t)n * CH + t] - mf;

    float v0 = xd * xd;
    #pragma unroll
    for (int o = 16; o > 0; o >>= 1) v0 += __shfl_xor_sync(0xffffffffu, v0, o);
    if ((t & 31) == 0) sred[t >> 5] = v0;
    __syncthreads();
    if (t == 0) stot = sred[0] + sred[1] + sred[2] + sred[3];

    if (t < 3) {
        float a = 0.f;
        #pragma unroll
        for (int k = 0; k < KN; k++)
            a += sval[k] * pts[(size_t)sidx[k] * 3 + t];
        float mp = a * inv;
        float d = pts[(size_t)n * 3 + t] - mp;
        sc[t] = d * d;
    }
    __syncthreads();

    float fd = sqrtf(stot);
    float cd = sqrtf(sc[0] + sc[1] + sc[2]);

    float h = gelu_exact(fd * bw1[t] + cd * bw1[CH + t] + bb1[t]);
    float v1 = h * bw2[t];
    __syncthreads();
    #pragma unroll
    for (int o = 16; o > 0; o >>= 1) v1 += __shfl_xor_sync(0xffffffffu, v1, o);
    if ((t & 31) == 0) sred[t >> 5] = v1;
    __syncthreads();
    if (t == 0) g_bnd[n] = sigm(sred[0] + sred[1] + sred[2] + sred[3] + bb2[0]);
}

// ---------------- K_pack: fp32 [128K x 128N] row-major -> mma B-fragment order
// dst[(ns*8+kk)*32 + lane] = {b0, b1} for mma.m16n8k16 (row.col), where
//   g=lane>>2, tig=lane&3, n=ns*8+g, k0=kk*16+tig*2
//   b0 = (W[k0][n], W[k0+1][n]); b1 = (W[k0+8][n], W[k0+9][n])
__global__ void k_pack(const float* __restrict__ w0, const float* __restrict__ w1,
                       const float* __restrict__ w2, const float* __restrict__ w3,
                       const float* __restrict__ w4, const float* __restrict__ w5,
                       const float* __restrict__ w6, const float* __restrict__ w7,
                       const float* __restrict__ w8) {
    const float* W;
    switch (blockIdx.y) {
        case 0: W = w0; break;  case 1: W = w1; break;  case 2: W = w2; break;
        case 3: W = w3; break;  case 4: W = w4; break;  case 5: W = w5; break;
        case 6: W = w6; break;  case 7: W = w7; break;  default: W = w8; break;
    }
    int idx = blockIdx.x * 256 + threadIdx.x;      // 0..4095
    int lane = idx & 31;
    int kk   = (idx >> 5) & 7;
    int ns   = idx >> 8;
    int g = lane >> 2, tig = lane & 3;
    int n  = ns * 8 + g;
    int k0 = kk * 16 + tig * 2;
    __nv_bfloat162 lo, hi;
    lo.x = __float2bfloat16(W[(size_t)k0 * CH + n]);
    lo.y = __float2bfloat16(W[(size_t)(k0 + 1) * CH + n]);
    hi.x = __float2bfloat16(W[(size_t)(k0 + 8) * CH + n]);
    hi.y = __float2bfloat16(W[(size_t)(k0 + 9) * CH + n]);
    uint2 v;
    v.x = *reinterpret_cast<uint32_t*>(&lo);
    v.y = *reinterpret_cast<uint32_t*>(&hi);
    g_pk[blockIdx.y * 4096 + idx] = v;
}

// ---------------- mma helpers ------------------------------------------------
__device__ __forceinline__ void mma16816(float (&c)[4], const uint32_t (&a)[4],
                                         uint32_t b0, uint32_t b1) {
    asm volatile(
        "mma.sync.aligned.m16n8k16.row.col.f32.bf16.bf16.f32 "
        "{%0,%1,%2,%3}, {%4,%5,%6,%7}, {%8,%9}, {%0,%1,%2,%3};\n"
        : "+f"(c[0]), "+f"(c[1]), "+f"(c[2]), "+f"(c[3])
        : "r"(a[0]), "r"(a[1]), "r"(a[2]), "r"(a[3]), "r"(b0), "r"(b1));
}

#define ASTRIDE 136   // bf16 elems per row: 272B -> bank = (4r+tig)%32, conflict-free

__device__ __forceinline__ void frag_init(float (&c)[2][4][4],
                                          const float* __restrict__ bias,
                                          const float* __restrict__ wb,
                                          const float* bndp,
                                          int warp, int g, int tig) {
    #pragma unroll
    for (int sub = 0; sub < 4; sub++) {
        int nA = warp * 32 + sub * 8 + tig * 2;
        float bA = bias[nA], bB = bias[nA + 1];
        float wA = wb ? wb[nA] : 0.f, wB = wb ? wb[nA + 1] : 0.f;
        #pragma unroll
        for (int mt = 0; mt < 2; mt++) {
            float e0 = bndp ? bndp[mt * 16 + g] : 0.f;
            float e8 = bndp ? bndp[mt * 16 + g + 8] : 0.f;
            c[mt][sub][0] = bA + e0 * wA;
            c[mt][sub][1] = bB + e0 * wB;
            c[mt][sub][2] = bA + e8 * wA;
            c[mt][sub][3] = bB + e8 * wB;
        }
    }
}

__device__ __forceinline__ void gemm_acc(float (&c)[2][4][4],
                                         const __nv_bfloat16 (&A)[BP][ASTRIDE],
                                         const uint2* __restrict__ pk,
                                         int warp, int lane, int g, int tig) {
    #pragma unroll
    for (int kk = 0; kk < 8; kk++) {
        uint32_t a[2][4];
        #pragma unroll
        for (int mt = 0; mt < 2; mt++) {
            int r = mt * 16 + g;
            int kb = kk * 16 + tig * 2;
            a[mt][0] = *reinterpret_cast<const uint32_t*>(&A[r][kb]);
            a[mt][1] = *reinterpret_cast<const uint32_t*>(&A[r + 8][kb]);
            a[mt][2] = *reinterpret_cast<const uint32_t*>(&A[r][kb + 8]);
            a[mt][3] = *reinterpret_cast<const uint32_t*>(&A[r + 8][kb + 8]);
        }
        #pragma unroll
        for (int sub = 0; sub < 4; sub++) {
            uint2 b = pk[((warp * 4 + sub) * 8 + kk) * 32 + lane];
            mma16816(c[0][sub], a[0], b.x, b.y);
            mma16816(c[1][sub], a[1], b.x, b.y);
        }
    }
}

__device__ __forceinline__ void frag_store(__nv_bfloat16 (&D)[BP][ASTRIDE],
                                           const float (&c)[2][4][4], int act,
                                           int warp, int g, int tig) {
    #pragma unroll
    for (int sub = 0; sub < 4; sub++) {
        int nA = warp * 32 + sub * 8 + tig * 2;
        #pragma unroll
        for (int mt = 0; mt < 2; mt++) {
            int r = mt * 16 + g;
            float v0 = c[mt][sub][0], v1 = c[mt][sub][1];
            float v2 = c[mt][sub][2], v3 = c[mt][sub][3];
            if (act) { v0 = gelu_exact(v0); v1 = gelu_exact(v1);
                       v2 = gelu_exact(v2); v3 = gelu_exact(v3); }
            __nv_bfloat162 p01, p23;
            p01.x = __float2bfloat16(v0); p01.y = __float2bfloat16(v1);
            p23.x = __float2bfloat16(v2); p23.y = __float2bfloat16(v3);
            *reinterpret_cast<uint32_t*>(&D[r][nA])     = *reinterpret_cast<uint32_t*>(&p01);
            *reinterpret_cast<uint32_t*>(&D[r + 8][nA]) = *reinterpret_cast<uint32_t*>(&p23);
        }
    }
}

// ---------------- K6: fused MLPs via bf16 tensor cores -----------------------
__global__ __launch_bounds__(128)
void k_mlp(const float* __restrict__ pts, const float* __restrict__ feats,
           const float* __restrict__ cpw1, const float* __restrict__ cpb1,
           const float* __restrict__ cpb2,
           const float* __restrict__ mw1,  const float* __restrict__ mb1,
           const float* __restrict__ mb2,
           const float* __restrict__ gw1,  const float* __restrict__ gb1,
           const float* __restrict__ gb2,
           const float* __restrict__ ob,
           float* __restrict__ out) {
    __shared__ alignas(16) __nv_bfloat16 xs[BP][ASTRIDE];
    __shared__ alignas(16) __nv_bfloat16 ms[BP][ASTRIDE];
    __shared__ alignas(16) __nv_bfloat16 cs[BP][ASTRIDE];
    __shared__ alignas(16) __nv_bfloat16 hs[BP][ASTRIDE];
    __shared__ alignas(16) __nv_bfloat16 rs[BP][ASTRIDE];
    __shared__ float bnd[BP];
    __shared__ float cpt[BP][3];

    int t = threadIdx.x;
    int lane = t & 31, warp = t >> 5, g = lane >> 2, tig = lane & 3;
    int p0 = blockIdx.x * BP;

    #pragma unroll 4
    for (int p = 0; p < BP; p++) {
        xs[p][t] = __float2bfloat16(g_x [(size_t)(p0 + p) * CH + t]);
        ms[p][t] = __float2bfloat16(g_mf[(size_t)(p0 + p) * CH + t]);
    }
    if (t < BP) bnd[t] = g_bnd[p0 + t];
    if (t < BP * 3) {
        int p = t / 3, d = t - 3 * p;
        float mean = g_sum3[d] * (1.0f / NPTS);
        float scl  = fmaxf(__uint_as_float(g_max3[d]), 1e-6f);
        cpt[p][d] = (pts[(size_t)(p0 + p) * 3 + d] - mean) / scl;
    }
    __syncthreads();

    // coord-embed hidden (3 -> 128), SIMT
    {
        float w0 = cpw1[t], w1 = cpw1[CH + t], w2 = cpw1[2 * CH + t], b = cpb1[t];
        #pragma unroll 4
        for (int p = 0; p < BP; p++)
            hs[p][t] = __float2bfloat16(
                gelu_exact(cpt[p][0] * w0 + cpt[p][1] * w1 + cpt[p][2] * w2 + b));
    }
    __syncthreads();

    float c[2][4][4], rf[2][4][4];

    // coord_embed = hidden @ cp_w2 + cp_b2
    frag_init(c, cpb2, nullptr, nullptr, warp, g, tig);
    gemm_acc(c, hs, g_pk + 0 * 4096, warp, lane, g, tig);
    frag_store(cs, c, 0, warp, g, tig);
    __syncthreads();

    // mix hidden: [x | mf | bnd | ce] @ mix_w1 + b -> gelu
    frag_init(c, mb1, mw1 + 256 * CH, bnd, warp, g, tig);
    gemm_acc(c, xs, g_pk + 1 * 4096, warp, lane, g, tig);
    gemm_acc(c, ms, g_pk + 2 * 4096, warp, lane, g, tig);
    gemm_acc(c, cs, g_pk + 3 * 4096, warp, lane, g, tig);
    frag_store(hs, c, 1, warp, g, tig);
    __syncthreads();

    // refined = mix_hidden @ mix_w2 + b (kept in fragments)
    frag_init(rf, mb2, nullptr, nullptr, warp, g, tig);
    gemm_acc(rf, hs, g_pk + 4 * 4096, warp, lane, g, tig);
    __syncthreads();   // all warps done reading hs before overwrite

    // gate hidden: [x | mf | bnd] @ gate_w1 + b -> gelu
    frag_init(c, gb1, gw1 + 256 * CH, bnd, warp, g, tig);
    gemm_acc(c, xs, g_pk + 5 * 4096, warp, lane, g, tig);
    gemm_acc(c, ms, g_pk + 6 * 4096, warp, lane, g, tig);
    frag_store(hs, c, 1, warp, g, tig);
    __syncthreads();

    // gate = sigmoid(gate_hidden @ gate_w2 + b); rs = gate * refined
    frag_init(c, gb2, nullptr, nullptr, warp, g, tig);
    gemm_acc(c, hs, g_pk + 7 * 4096, warp, lane, g, tig);
    #pragma unroll
    for (int mt = 0; mt < 2; mt++)
        #pragma unroll
        for (int sub = 0; sub < 4; sub++)
            #pragma unroll
            for (int i = 0; i < 4; i++)
                rf[mt][sub][i] = sigm(c[mt][sub][i]) * rf[mt][sub][i];
    frag_store(rs, rf, 0, warp, g, tig);
    __syncthreads();

    // out = feats + rs @ out_w + out_b
    frag_init(c, ob, nullptr, nullptr, warp, g, tig);
    gemm_acc(c, rs, g_pk + 8 * 4096, warp, lane, g, tig);
    #pragma unroll
    for (int sub = 0; sub < 4; sub++) {
        int nA = warp * 32 + sub * 8 + tig * 2;
        #pragma unroll
        for (int mt = 0; mt < 2; mt++) {
            int r = mt * 16 + g;
            size_t ro0 = (size_t)(p0 + r) * CH + nA;
            size_t ro8 = (size_t)(p0 + r + 8) * CH + nA;
            float2 f0 = *reinterpret_cast<const float2*>(feats + ro0);
            float2 f8 = *reinterpret_cast<const float2*>(feats + ro8);
            float2 o0, o8;
            o0.x = f0.x + c[mt][sub][0]; o0.y = f0.y + c[mt][sub][1];
            o8.x = f8.x + c[mt][sub][2]; o8.y = f8.y + c[mt][sub][3];
            *reinterpret_cast<float2*>(out + ro0) = o0;
            *reinterpret_cast<float2*>(out + ro8) = o8;
        }
    }
}

// ---------------- launch -----------------------------------------------------
extern "C" void kernel_launch(void* const* d_in, const int* in_sizes, int n_in,
                              void* d_out, int out_size) {
    const float* feats = (const float*)d_in[0];
    const float* pts   = (const float*)d_in[1];
    const int*   nbr   = (const int*)d_in[2];     // int64 downcast to int32 by harness
    const float* ln_g  = (const float*)d_in[3];
    const float* ln_b  = (const float*)d_in[4];
    const float* cpw1  = (const float*)d_in[5];
    const float* cpb1  = (const float*)d_in[6];
    const float* cpw2  = (const float*)d_in[7];
    const float* cpb2  = (const float*)d_in[8];
    const float* bw1   = (const float*)d_in[9];
    const float* bb1   = (const float*)d_in[10];
    const float* bw2   = (const float*)d_in[11];
    const float* bb2   = (const float*)d_in[12];
    const float* mw1   = (const float*)d_in[13];
    const float* mb1   = (const float*)d_in[14];
    const float* mw2   = (const float*)d_in[15];
    const float* mb2   = (const float*)d_in[16];
    const float* gw1   = (const float*)d_in[17];
    const float* gb1   = (const float*)d_in[18];
    const float* gw2   = (const float*)d_in[19];
    const float* gb2   = (const float*)d_in[20];
    const float* ow    = (const float*)d_in[21];
    const float* ob    = (const float*)d_in[22];
    float* out = (float*)d_out;

    (void)in_sizes; (void)n_in; (void)out_size;

    k_reset<<<1, 32>>>();
    // pack the 9 [128x128] weight sections into mma B-fragment order (bf16)
    {
        dim3 grid(16, 9);
        k_pack<<<grid, 256>>>(cpw2,
                              mw1,                 // mix rows   0..127 (x)
                              mw1 + 128 * CH,      // mix rows 128..255 (mf)
                              mw1 + 257 * CH,      // mix rows 257..384 (ce)
                              mw2,
                              gw1,                 // gate rows  0..127 (x)
                              gw1 + 128 * CH,      // gate rows 128..255 (mf)
                              gw2,
                              ow);
    }
    k_psum<<<NBLK_RED, 256>>>(pts);
    k_psum2<<<1, NBLK_RED>>>();
    k_max<<<NBLK_RED, 256>>>(pts);
    k_ln<<<(NPTS + 7) / 8, 256>>>(feats, ln_g, ln_b);
    k_gather<<<NPTS, 128>>>(pts, nbr, bw1, bb1, bw2, bb2);
    k_mlp<<<(NPTS + BP - 1) / BP, 128>>>(pts, feats,
                                         cpw1, cpb1, cpb2,
                                         mw1, mb1, mb2,
                                         gw1, gb1, gb2,
                                         ob, out);
}

// round 6
// speedup vs baseline: 3.3498x; 1.0731x over previous
#include <cuda_runtime.h>
#include <cuda_bf16.h>
#include <math.h>
#include <stdint.h>

#define NPTS 100000
#define NPAD 100032          // 64-aligned padding (device globals zero-init)
#define CH   128
#define KN   16
#define BP   64              // points per k_mlp block (four m16 tiles)
#define NBLK_RED 256
#define ASTRIDE 136          // bf16 elems per smem row (272B) -> conflict-free

// ---------------- scratch (device globals; no allocations allowed) ----------
__device__ __nv_bfloat16 g_xb [(size_t)NPAD * CH];  // LayerNorm output (bf16)
__device__ __nv_bfloat16 g_mfb[(size_t)NPAD * CH];  // neighbor mean feature (bf16)
__device__ float         g_bnd[NPAD];               // boundary score
__device__ float         g_part[NBLK_RED * 3];
__device__ float         g_sum3[3];
__device__ unsigned int  g_max3[3];
__device__ uint2         g_pk[9 * 4096];            // fragment-packed bf16 weights

__device__ __forceinline__ float gelu_exact(float v) {
    return 0.5f * v * (1.0f + erff(v * 0.70710678118654752f));
}
__device__ __forceinline__ float sigm(float v) {
    return 1.0f / (1.0f + __expf(-v));
}

// ---------------- K0: reset accumulators ------------------------------------
__global__ void k_reset() {
    if (threadIdx.x < 3) { g_sum3[threadIdx.x] = 0.0f; g_max3[threadIdx.x] = 0u; }
}

// ---------------- K1: per-block partial sums of points ----------------------
__global__ void k_psum(const float* __restrict__ pts) {
    float s0 = 0.f, s1 = 0.f, s2 = 0.f;
    for (int i = blockIdx.x * blockDim.x + threadIdx.x; i < NPTS;
         i += gridDim.x * blockDim.x) {
        s0 += pts[3 * i + 0];
        s1 += pts[3 * i + 1];
        s2 += pts[3 * i + 2];
    }
    __shared__ float sh[8][3];
    #pragma unroll
    for (int o = 16; o > 0; o >>= 1) {
        s0 += __shfl_xor_sync(0xffffffffu, s0, o);
        s1 += __shfl_xor_sync(0xffffffffu, s1, o);
        s2 += __shfl_xor_sync(0xffffffffu, s2, o);
    }
    int w = threadIdx.x >> 5, l = threadIdx.x & 31;
    if (l == 0) { sh[w][0] = s0; sh[w][1] = s1; sh[w][2] = s2; }
    __syncthreads();
    if (threadIdx.x == 0) {
        float t0 = 0.f, t1 = 0.f, t2 = 0.f;
        #pragma unroll
        for (int i = 0; i < 8; i++) { t0 += sh[i][0]; t1 += sh[i][1]; t2 += sh[i][2]; }
        g_part[blockIdx.x * 3 + 0] = t0;
        g_part[blockIdx.x * 3 + 1] = t1;
        g_part[blockIdx.x * 3 + 2] = t2;
    }
}

// ---------------- K2: combine partials --------------------------------------
__global__ void k_psum2() {
    float s0 = g_part[threadIdx.x * 3 + 0];
    float s1 = g_part[threadIdx.x * 3 + 1];
    float s2 = g_part[threadIdx.x * 3 + 2];
    __shared__ float sh[8][3];
    #pragma unroll
    for (int o = 16; o > 0; o >>= 1) {
        s0 += __shfl_xor_sync(0xffffffffu, s0, o);
        s1 += __shfl_xor_sync(0xffffffffu, s1, o);
        s2 += __shfl_xor_sync(0xffffffffu, s2, o);
    }
    int w = threadIdx.x >> 5, l = threadIdx.x & 31;
    if (l == 0) { sh[w][0] = s0; sh[w][1] = s1; sh[w][2] = s2; }
    __syncthreads();
    if (threadIdx.x == 0) {
        float t0 = 0.f, t1 = 0.f, t2 = 0.f;
        #pragma unroll
        for (int i = 0; i < 8; i++) { t0 += sh[i][0]; t1 += sh[i][1]; t2 += sh[i][2]; }
        g_sum3[0] = t0; g_sum3[1] = t1; g_sum3[2] = t2;
    }
}

// ---------------- K3: max |p - mean| per dim --------------------------------
__global__ void k_max(const float* __restrict__ pts) {
    float m0 = g_sum3[0] * (1.0f / NPTS);
    float m1 = g_sum3[1] * (1.0f / NPTS);
    float m2 = g_sum3[2] * (1.0f / NPTS);
    float a0 = 0.f, a1 = 0.f, a2 = 0.f;
    for (int i = blockIdx.x * blockDim.x + threadIdx.x; i < NPTS;
         i += gridDim.x * blockDim.x) {
        a0 = fmaxf(a0, fabsf(pts[3 * i + 0] - m0));
        a1 = fmaxf(a1, fabsf(pts[3 * i + 1] - m1));
        a2 = fmaxf(a2, fabsf(pts[3 * i + 2] - m2));
    }
    #pragma unroll
    for (int o = 16; o > 0; o >>= 1) {
        a0 = fmaxf(a0, __shfl_xor_sync(0xffffffffu, a0, o));
        a1 = fmaxf(a1, __shfl_xor_sync(0xffffffffu, a1, o));
        a2 = fmaxf(a2, __shfl_xor_sync(0xffffffffu, a2, o));
    }
    __shared__ float sh[8][3];
    int w = threadIdx.x >> 5, l = threadIdx.x & 31;
    if (l == 0) { sh[w][0] = a0; sh[w][1] = a1; sh[w][2] = a2; }
    __syncthreads();
    if (threadIdx.x == 0) {
        float t0 = 0.f, t1 = 0.f, t2 = 0.f;
        #pragma unroll
        for (int i = 0; i < 8; i++) {
            t0 = fmaxf(t0, sh[i][0]); t1 = fmaxf(t1, sh[i][1]); t2 = fmaxf(t2, sh[i][2]);
        }
        atomicMax(&g_max3[0], __float_as_uint(t0));
        atomicMax(&g_max3[1], __float_as_uint(t1));
        atomicMax(&g_max3[2], __float_as_uint(t2));
    }
}

// ---------------- K4: LayerNorm, warp per row, float4 in / bf16x4 out -------
__global__ void k_ln(const float* __restrict__ feats,
                     const float* __restrict__ gg, const float* __restrict__ bb) {
    int row = blockIdx.x * 8 + (threadIdx.x >> 5);
    if (row >= NPTS) return;
    int l = threadIdx.x & 31;
    float4 v = reinterpret_cast<const float4*>(feats + (size_t)row * CH)[l];
    float s = v.x + v.y + v.z + v.w;
    #pragma unroll
    for (int o = 16; o > 0; o >>= 1) s += __shfl_xor_sync(0xffffffffu, s, o);
    float mean = s * (1.0f / CH);
    float dx = v.x - mean, dy = v.y - mean, dz = v.z - mean, dw = v.w - mean;
    float q = dx * dx + dy * dy + dz * dz + dw * dw;
    #pragma unroll
    for (int o = 16; o > 0; o >>= 1) q += __shfl_xor_sync(0xffffffffu, q, o);
    float rstd = rsqrtf(q * (1.0f / CH) + 1e-5f);
    float4 g4 = reinterpret_cast<const float4*>(gg)[l];
    float4 b4 = reinterpret_cast<const float4*>(bb)[l];
    __nv_bfloat162 lo, hi;
    lo.x = __float2bfloat16(dx * rstd * g4.x + b4.x);
    lo.y = __float2bfloat16(dy * rstd * g4.y + b4.y);
    hi.x = __float2bfloat16(dz * rstd * g4.z + b4.z);
    hi.y = __float2bfloat16(dw * rstd * g4.w + b4.w);
    uint2 u;
    u.x = *reinterpret_cast<uint32_t*>(&lo);
    u.y = *reinterpret_cast<uint32_t*>(&hi);
    reinterpret_cast<uint2*>(g_xb + (size_t)row * CH)[l] = u;
}

// ---------------- K5: gather (bf16 pairs) + boundary MLP, 64 threads --------
__global__ __launch_bounds__(64)
void k_gather(const float* __restrict__ pts,
              const int* __restrict__ nbr,
              const float* __restrict__ bw1, const float* __restrict__ bb1,
              const float* __restrict__ bw2, const float* __restrict__ bb2) {
    int n = blockIdx.x;
    int t = threadIdx.x;  // 64 threads
    __shared__ int   sidx[KN];
    __shared__ float sval[KN];
    __shared__ float sc[3];
    __shared__ float sred[2];
    __shared__ float stot;

    if (t < KN) {
        int v = nbr[(size_t)n * KN + t];
        sval[t] = (v >= 0 && v < NPTS) ? 1.0f : 0.0f;
        sidx[t] = v < 0 ? 0 : (v >= NPTS ? (NPTS - 1) : v);
    }
    __syncthreads();

    float denom = 0.f;
    #pragma unroll
    for (int k = 0; k < KN; k++) denom += sval[k];
    denom = fmaxf(denom, 1.0f);
    float inv = 1.0f / denom;

    const uint32_t* xb32 = reinterpret_cast<const uint32_t*>(g_xb);
    float a0 = 0.f, a1 = 0.f;
    #pragma unroll
    for (int k = 0; k < KN; k++) {
        uint32_t u = xb32[(size_t)sidx[k] * 64 + t];
        __nv_bfloat162 b = *reinterpret_cast<__nv_bfloat162*>(&u);
        a0 += sval[k] * __bfloat162float(b.x);
        a1 += sval[k] * __bfloat162float(b.y);
    }
    float mf0 = a0 * inv, mf1 = a1 * inv;
    __nv_bfloat162 mp;
    mp.x = __float2bfloat16(mf0);
    mp.y = __float2bfloat16(mf1);
    reinterpret_cast<uint32_t*>(g_mfb)[(size_t)n * 64 + t] =
        *reinterpret_cast<uint32_t*>(&mp);

    uint32_t xu = xb32[(size_t)n * 64 + t];
    __nv_bfloat162 xp = *reinterpret_cast<__nv_bfloat162*>(&xu);
    float d0 = __bfloat162float(xp.x) - mf0;
    float d1 = __bfloat162float(xp.y) - mf1;
    float v0 = d0 * d0 + d1 * d1;
    #pragma unroll
    for (int o = 16; o > 0; o >>= 1) v0 += __shfl_xor_sync(0xffffffffu, v0, o);
    if ((t & 31) == 0) sred[t >> 5] = v0;

    if (t < 3) {
        float a = 0.f;
        #pragma unroll
        for (int k = 0; k < KN; k++)
            a += sval[k] * pts[(size_t)sidx[k] * 3 + t];
        float mpt = a * inv;
        float d = pts[(size_t)n * 3 + t] - mpt;
        sc[t] = d * d;
    }
    __syncthreads();
    if (t == 0) stot = sred[0] + sred[1];
    __syncthreads();

    float fd = sqrtf(stot);
    float cd = sqrtf(sc[0] + sc[1] + sc[2]);

    // boundary MLP: thread t handles hidden units t and t+64
    float h0 = gelu_exact(fd * bw1[t]      + cd * bw1[CH + t]      + bb1[t]);
    float h1 = gelu_exact(fd * bw1[t + 64] + cd * bw1[CH + t + 64] + bb1[t + 64]);
    float v1 = h0 * bw2[t] + h1 * bw2[t + 64];
    #pragma unroll
    for (int o = 16; o > 0; o >>= 1) v1 += __shfl_xor_sync(0xffffffffu, v1, o);
    __syncthreads();  // sred reads done before rewrite
    if ((t & 31) == 0) sred[t >> 5] = v1;
    __syncthreads();
    if (t == 0) g_bnd[n] = sigm(sred[0] + sred[1] + bb2[0]);
}

// ---------------- K_pack: fp32 [128K x 128N] -> mma B-fragment order ---------
__global__ void k_pack(const float* __restrict__ w0, const float* __restrict__ w1,
                       const float* __restrict__ w2, const float* __restrict__ w3,
                       const float* __restrict__ w4, const float* __restrict__ w5,
                       const float* __restrict__ w6, const float* __restrict__ w7,
                       const float* __restrict__ w8) {
    const float* W;
    switch (blockIdx.y) {
        case 0: W = w0; break;  case 1: W = w1; break;  case 2: W = w2; break;
        case 3: W = w3; break;  case 4: W = w4; break;  case 5: W = w5; break;
        case 6: W = w6; break;  case 7: W = w7; break;  default: W = w8; break;
    }
    int idx = blockIdx.x * 256 + threadIdx.x;      // 0..4095
    int lane = idx & 31;
    int kk   = (idx >> 5) & 7;
    int ns   = idx >> 8;
    int g = lane >> 2, tig = lane & 3;
    int n  = ns * 8 + g;
    int k0 = kk * 16 + tig * 2;
    __nv_bfloat162 lo, hi;
    lo.x = __float2bfloat16(W[(size_t)k0 * CH + n]);
    lo.y = __float2bfloat16(W[(size_t)(k0 + 1) * CH + n]);
    hi.x = __float2bfloat16(W[(size_t)(k0 + 8) * CH + n]);
    hi.y = __float2bfloat16(W[(size_t)(k0 + 9) * CH + n]);
    uint2 v;
    v.x = *reinterpret_cast<uint32_t*>(&lo);
    v.y = *reinterpret_cast<uint32_t*>(&hi);
    g_pk[blockIdx.y * 4096 + idx] = v;
}

// ---------------- mma helpers ------------------------------------------------
__device__ __forceinline__ void mma16816(float (&c)[4], const uint32_t (&a)[4],
                                         uint32_t b0, uint32_t b1) {
    asm volatile(
        "mma.sync.aligned.m16n8k16.row.col.f32.bf16.bf16.f32 "
        "{%0,%1,%2,%3}, {%4,%5,%6,%7}, {%8,%9}, {%0,%1,%2,%3};\n"
        : "+f"(c[0]), "+f"(c[1]), "+f"(c[2]), "+f"(c[3])
        : "r"(a[0]), "r"(a[1]), "r"(a[2]), "r"(a[3]), "r"(b0), "r"(b1));
}

__device__ __forceinline__ void ldm4(uint32_t (&r)[4], uint32_t addr) {
    asm volatile("ldmatrix.sync.aligned.m8n8.x4.shared.b16 {%0,%1,%2,%3}, [%4];"
                 : "=r"(r[0]), "=r"(r[1]), "=r"(r[2]), "=r"(r[3]) : "r"(addr));
}

__device__ __forceinline__ void frag_init(float (&c)[4][2][4],
                                          const float* __restrict__ bias,
                                          const float* __restrict__ wb,
                                          const float* bndp,
                                          int warp, int g, int tig) {
    #pragma unroll
    for (int sub = 0; sub < 2; sub++) {
        int nA = warp * 16 + sub * 8 + tig * 2;
        float bA = bias[nA], bB = bias[nA + 1];
        float wA = wb ? wb[nA] : 0.f, wB = wb ? wb[nA + 1] : 0.f;
        #pragma unroll
        for (int mt = 0; mt < 4; mt++) {
            float e0 = bndp ? bndp[mt * 16 + g] : 0.f;
            float e8 = bndp ? bndp[mt * 16 + g + 8] : 0.f;
            c[mt][sub][0] = bA + e0 * wA;
            c[mt][sub][1] = bB + e0 * wB;
            c[mt][sub][2] = bA + e8 * wA;
            c[mt][sub][3] = bB + e8 * wB;
        }
    }
}

// A from smem via ldmatrix.x4; B from fragment-packed global (L2-hot)
__device__ __forceinline__ void gemm_acc(float (&c)[4][2][4], uint32_t abase,
                                         const uint2* __restrict__ pk,
                                         int warp, int lane) {
    int rsel = (lane & 7) + ((lane >> 3) & 1) * 8;
    int csel = (lane >> 4) * 8;
    uint32_t off0 = abase + (uint32_t)((rsel * ASTRIDE + csel) * 2);
    #pragma unroll
    for (int kk = 0; kk < 8; kk++) {
        uint32_t a[4][4];
        #pragma unroll
        for (int mt = 0; mt < 4; mt++)
            ldm4(a[mt], off0 + mt * (16 * ASTRIDE * 2) + kk * 32);
        #pragma unroll
        for (int sub = 0; sub < 2; sub++) {
            uint2 b = pk[((warp * 2 + sub) * 8 + kk) * 32 + lane];
            #pragma unroll
            for (int mt = 0; mt < 4; mt++)
                mma16816(c[mt][sub], a[mt], b.x, b.y);
        }
    }
}

__device__ __forceinline__ void frag_store(__nv_bfloat16 (*D)[ASTRIDE],
                                           const float (&c)[4][2][4], int act,
                                           int warp, int g, int tig) {
    #pragma unroll
    for (int sub = 0; sub < 2; sub++) {
        int nA = warp * 16 + sub * 8 + tig * 2;
        #pragma unroll
        for (int mt = 0; mt < 4; mt++) {
            int r = mt * 16 + g;
            float v0 = c[mt][sub][0], v1 = c[mt][sub][1];
            float v2 = c[mt][sub][2], v3 = c[mt][sub][3];
            if (act) { v0 = gelu_exact(v0); v1 = gelu_exact(v1);
                       v2 = gelu_exact(v2); v3 = gelu_exact(v3); }
            __nv_bfloat162 p01, p23;
            p01.x = __float2bfloat16(v0); p01.y = __float2bfloat16(v1);
            p23.x = __float2bfloat16(v2); p23.y = __float2bfloat16(v3);
            *reinterpret_cast<uint32_t*>(&D[r][nA])     = *reinterpret_cast<uint32_t*>(&p01);
            *reinterpret_cast<uint32_t*>(&D[r + 8][nA]) = *reinterpret_cast<uint32_t*>(&p23);
        }
    }
}

// ---------------- K6: fused MLPs, BP=64, 256 threads, dynamic smem ----------
#define SMEM_ARR (BP * ASTRIDE * 2)          // 17408
#define SMEM_MLP (4 * SMEM_ARR + 256 + 768)  // xs,ms,cs,hs + bnd + cpt = 70656

__global__ __launch_bounds__(256, 2)
void k_mlp(const float* __restrict__ pts, const float* __restrict__ feats,
           const float* __restrict__ cpw1, const float* __restrict__ cpb1,
           const float* __restrict__ cpb2,
           const float* __restrict__ mw1,  const float* __restrict__ mb1,
           const float* __restrict__ mb2,
           const float* __restrict__ gw1,  const float* __restrict__ gb1,
           const float* __restrict__ gb2,
           const float* __restrict__ ob,
           float* __restrict__ out) {
    extern __shared__ char dyn[];
    __nv_bfloat16 (*xs)[ASTRIDE] = reinterpret_cast<__nv_bfloat16(*)[ASTRIDE]>(dyn);
    __nv_bfloat16 (*ms)[ASTRIDE] = reinterpret_cast<__nv_bfloat16(*)[ASTRIDE]>(dyn + SMEM_ARR);
    __nv_bfloat16 (*cs)[ASTRIDE] = reinterpret_cast<__nv_bfloat16(*)[ASTRIDE]>(dyn + 2 * SMEM_ARR);
    __nv_bfloat16 (*hs)[ASTRIDE] = reinterpret_cast<__nv_bfloat16(*)[ASTRIDE]>(dyn + 3 * SMEM_ARR);
    float* bnd       = reinterpret_cast<float*>(dyn + 4 * SMEM_ARR);
    float (*cpt)[3]  = reinterpret_cast<float(*)[3]>(dyn + 4 * SMEM_ARR + 256);

    int t = threadIdx.x;
    int lane = t & 31, warp = t >> 5, g = lane >> 2, tig = lane & 3;
    int p0 = blockIdx.x * BP;

    uint32_t a_xs = (uint32_t)__cvta_generic_to_shared(xs);
    uint32_t a_ms = (uint32_t)__cvta_generic_to_shared(ms);
    uint32_t a_cs = (uint32_t)__cvta_generic_to_shared(cs);
    uint32_t a_hs = (uint32_t)__cvta_generic_to_shared(hs);

    // load x / mf tiles as bf16x2 words (pad rows are zero-initialized globals)
    {
        const uint32_t* xb32 = reinterpret_cast<const uint32_t*>(g_xb);
        const uint32_t* mb32 = reinterpret_cast<const uint32_t*>(g_mfb);
        int pair = t & 63, pr0 = t >> 6;
        #pragma unroll
        for (int p = pr0; p < BP; p += 4) {
            uint32_t vx = xb32[(size_t)(p0 + p) * 64 + pair];
            uint32_t vm = mb32[(size_t)(p0 + p) * 64 + pair];
            *reinterpret_cast<uint32_t*>(&xs[p][pair * 2]) = vx;
            *reinterpret_cast<uint32_t*>(&ms[p][pair * 2]) = vm;
        }
    }
    if (t < BP) bnd[t] = g_bnd[p0 + t];
    if (t < BP * 3) {
        int p = t / 3, d = t - 3 * p;
        int row = min(p0 + p, NPTS - 1);
        float mean = g_sum3[d] * (1.0f / NPTS);
        float scl  = fmaxf(__uint_as_float(g_max3[d]), 1e-6f);
        cpt[p][d] = (pts[(size_t)row * 3 + d] - mean) / scl;
    }
    __syncthreads();

    // coord-embed hidden (3 -> 128), SIMT
    {
        int col = t & 127, half = t >> 7;
        float w0 = cpw1[col], w1 = cpw1[CH + col], w2 = cpw1[2 * CH + col], b = cpb1[col];
        #pragma unroll
        for (int p = half; p < BP; p += 2)
            hs[p][col] = __float2bfloat16(
                gelu_exact(cpt[p][0] * w0 + cpt[p][1] * w1 + cpt[p][2] * w2 + b));
    }
    __syncthreads();

    float c[4][2][4], rf[4][2][4];

    // coord_embed = hidden @ cp_w2 + cp_b2
    frag_init(c, cpb2, nullptr, nullptr, warp, g, tig);
    gemm_acc(c, a_hs, g_pk + 0 * 4096, warp, lane);
    frag_store(cs, c, 0, warp, g, tig);
    __syncthreads();

    // mix hidden: [x | mf | bnd | ce] @ mix_w1 + b -> gelu
    frag_init(c, mb1, mw1 + 256 * CH, bnd, warp, g, tig);
    gemm_acc(c, a_xs, g_pk + 1 * 4096, warp, lane);
    gemm_acc(c, a_ms, g_pk + 2 * 4096, warp, lane);
    gemm_acc(c, a_cs, g_pk + 3 * 4096, warp, lane);
    frag_store(hs, c, 1, warp, g, tig);
    __syncthreads();

    // refined = mix_hidden @ mix_w2 + b (kept in registers)
    frag_init(rf, mb2, nullptr, nullptr, warp, g, tig);
    gemm_acc(rf, a_hs, g_pk + 4 * 4096, warp, lane);
    __syncthreads();   // all warps done reading hs before overwrite

    // gate hidden: [x | mf | bnd] @ gate_w1 + b -> gelu
    frag_init(c, gb1, gw1 + 256 * CH, bnd, warp, g, tig);
    gemm_acc(c, a_xs, g_pk + 5 * 4096, warp, lane);
    gemm_acc(c, a_ms, g_pk + 6 * 4096, warp, lane);
    frag_store(hs, c, 1, warp, g, tig);
    __syncthreads();

    // gate = sigmoid(gate_hidden @ gate_w2 + b); rf = gate * refined
    frag_init(c, gb2, nullptr, nullptr, warp, g, tig);
    gemm_acc(c, a_hs, g_pk + 7 * 4096, warp, lane);
    #pragma unroll
    for (int mt = 0; mt < 4; mt++)
        #pragma unroll
        for (int sub = 0; sub < 2; sub++)
            #pragma unroll
            for (int i = 0; i < 4; i++)
                rf[mt][sub][i] = sigm(c[mt][sub][i]) * rf[mt][sub][i];
    frag_store(cs, rf, 0, warp, g, tig);   // rs aliases cs (coord_embed dead)
    __syncthreads();

    // out = feats + rs @ out_w + out_b
    frag_init(c, ob, nullptr, nullptr, warp, g, tig);
    gemm_acc(c, a_cs, g_pk + 8 * 4096, warp, lane);
    #pragma unroll
    for (int sub = 0; sub < 2; sub++) {
        int nA = warp * 16 + sub * 8 + tig * 2;
        #pragma unroll
        for (int mt = 0; mt < 4; mt++) {
            int r = mt * 16 + g;
            int row0 = p0 + r, row8 = row0 + 8;
            if (row0 < NPTS) {
                size_t o = (size_t)row0 * CH + nA;
                float2 f = *reinterpret_cast<const float2*>(feats + o);
                float2 v; v.x = f.x + c[mt][sub][0]; v.y = f.y + c[mt][sub][1];
                *reinterpret_cast<float2*>(out + o) = v;
            }
            if (row8 < NPTS) {
                size_t o = (size_t)row8 * CH + nA;
                float2 f = *reinterpret_cast<const float2*>(feats + o);
                float2 v; v.x = f.x + c[mt][sub][2]; v.y = f.y + c[mt][sub][3];
                *reinterpret_cast<float2*>(out + o) = v;
            }
        }
    }
}

// ---------------- launch -----------------------------------------------------
extern "C" void kernel_launch(void* const* d_in, const int* in_sizes, int n_in,
                              void* d_out, int out_size) {
    const float* feats = (const float*)d_in[0];
    const float* pts   = (const float*)d_in[1];
    const int*   nbr   = (const int*)d_in[2];     // int64 downcast to int32 by harness
    const float* ln_g  = (const float*)d_in[3];
    const float* ln_b  = (const float*)d_in[4];
    const float* cpw1  = (const float*)d_in[5];
    const float* cpb1  = (const float*)d_in[6];
    const float* cpw2  = (const float*)d_in[7];
    const float* cpb2  = (const float*)d_in[8];
    const float* bw1   = (const float*)d_in[9];
    const float* bb1   = (const float*)d_in[10];
    const float* bw2   = (const float*)d_in[11];
    const float* bb2   = (const float*)d_in[12];
    const float* mw1   = (const float*)d_in[13];
    const float* mb1   = (const float*)d_in[14];
    const float* mw2   = (const float*)d_in[15];
    const float* mb2   = (const float*)d_in[16];
    const float* gw1   = (const float*)d_in[17];
    const float* gb1   = (const float*)d_in[18];
    const float* gw2   = (const float*)d_in[19];
    const float* gb2   = (const float*)d_in[20];
    const float* ow    = (const float*)d_in[21];
    const float* ob    = (const float*)d_in[22];
    float* out = (float*)d_out;

    (void)in_sizes; (void)n_in; (void)out_size;

    cudaFuncSetAttribute(k_mlp, cudaFuncAttributeMaxDynamicSharedMemorySize, SMEM_MLP);

    k_reset<<<1, 32>>>();
    {
        dim3 grid(16, 9);
        k_pack<<<grid, 256>>>(cpw2,
                              mw1,                 // mix rows   0..127 (x)
                              mw1 + 128 * CH,      // mix rows 128..255 (mf)
                              mw1 + 257 * CH,      // mix rows 257..384 (ce)
                              mw2,
                              gw1,                 // gate rows  0..127 (x)
                              gw1 + 128 * CH,      // gate rows 128..255 (mf)
                              gw2,
                              ow);
    }
    k_psum<<<NBLK_RED, 256>>>(pts);
    k_psum2<<<1, NBLK_RED>>>();
    k_max<<<NBLK_RED, 256>>>(pts);
    k_ln<<<(NPTS + 7) / 8, 256>>>(feats, ln_g, ln_b);
    k_gather<<<NPTS, 64>>>(pts, nbr, bw1, bb1, bw2, bb2);
    k_mlp<<<NPAD / BP, 256, SMEM_MLP>>>(pts, feats,
                                        cpw1, cpb1, cpb2,
                                        mw1, mb1, mb2,
                                        gw1, gb1, gb2,
                                        ob, out);
}

// round 7
// speedup vs baseline: 5.0083x; 1.4951x over previous
#include <cuda_runtime.h>
#include <cuda_bf16.h>
#include <math.h>
#include <stdint.h>

#define NPTS 100000
#define NPAD 100032          // 64-aligned padding (device globals zero-init)
#define CH   128
#define KN   16
#define BP   64              // points per k_mlp block (four m16 tiles)
#define NBLK_RED 256
#define ASTRIDE 136          // bf16 elems per smem row (272B) -> conflict-free

// ---------------- scratch (device globals; no allocations allowed) ----------
__device__ __nv_bfloat16 g_xb [(size_t)NPAD * CH];  // LayerNorm output (bf16)
__device__ __nv_bfloat16 g_mfb[(size_t)NPAD * CH];  // neighbor mean feature (bf16)
__device__ float         g_bnd[NPAD];               // boundary score
__device__ float         g_part[NBLK_RED * 9];      // per-block {sum3,min3,max3}
__device__ float         g_sum3[3];                 // total sum of points
__device__ float         g_scale[3];                // max |p - mean| per dim
__device__ uint2         g_pk[9 * 4096];            // fragment-packed bf16 weights

__device__ __forceinline__ float gelu_exact(float v) {
    return 0.5f * v * (1.0f + erff(v * 0.70710678118654752f));
}
__device__ __forceinline__ float sigm(float v) {
    return 1.0f / (1.0f + __expf(-v));
}

// ---------------- K1: per-block sum/min/max of points -----------------------
__global__ void k_psum(const float* __restrict__ pts) {
    float s0 = 0.f, s1 = 0.f, s2 = 0.f;
    float mn0 = 1e30f, mn1 = 1e30f, mn2 = 1e30f;
    float mx0 = -1e30f, mx1 = -1e30f, mx2 = -1e30f;
    for (int i = blockIdx.x * blockDim.x + threadIdx.x; i < NPTS;
         i += gridDim.x * blockDim.x) {
        float p0 = pts[3 * i + 0], p1 = pts[3 * i + 1], p2 = pts[3 * i + 2];
        s0 += p0; s1 += p1; s2 += p2;
        mn0 = fminf(mn0, p0); mn1 = fminf(mn1, p1); mn2 = fminf(mn2, p2);
        mx0 = fmaxf(mx0, p0); mx1 = fmaxf(mx1, p1); mx2 = fmaxf(mx2, p2);
    }
    __shared__ float sh[8][9];
    #pragma unroll
    for (int o = 16; o > 0; o >>= 1) {
        s0 += __shfl_xor_sync(0xffffffffu, s0, o);
        s1 += __shfl_xor_sync(0xffffffffu, s1, o);
        s2 += __shfl_xor_sync(0xffffffffu, s2, o);
        mn0 = fminf(mn0, __shfl_xor_sync(0xffffffffu, mn0, o));
        mn1 = fminf(mn1, __shfl_xor_sync(0xffffffffu, mn1, o));
        mn2 = fminf(mn2, __shfl_xor_sync(0xffffffffu, mn2, o));
        mx0 = fmaxf(mx0, __shfl_xor_sync(0xffffffffu, mx0, o));
        mx1 = fmaxf(mx1, __shfl_xor_sync(0xffffffffu, mx1, o));
        mx2 = fmaxf(mx2, __shfl_xor_sync(0xffffffffu, mx2, o));
    }
    int w = threadIdx.x >> 5, l = threadIdx.x & 31;
    if (l == 0) {
        sh[w][0] = s0;  sh[w][1] = s1;  sh[w][2] = s2;
        sh[w][3] = mn0; sh[w][4] = mn1; sh[w][5] = mn2;
        sh[w][6] = mx0; sh[w][7] = mx1; sh[w][8] = mx2;
    }
    __syncthreads();
    if (threadIdx.x == 0) {
        float r[9];
        #pragma unroll
        for (int j = 0; j < 9; j++) r[j] = sh[0][j];
        #pragma unroll
        for (int i = 1; i < 8; i++) {
            r[0] += sh[i][0]; r[1] += sh[i][1]; r[2] += sh[i][2];
            r[3] = fminf(r[3], sh[i][3]); r[4] = fminf(r[4], sh[i][4]);
            r[5] = fminf(r[5], sh[i][5]);
            r[6] = fmaxf(r[6], sh[i][6]); r[7] = fmaxf(r[7], sh[i][7]);
            r[8] = fmaxf(r[8], sh[i][8]);
        }
        #pragma unroll
        for (int j = 0; j < 9; j++) g_part[blockIdx.x * 9 + j] = r[j];
    }
}

// ---------------- K2: combine partials, finalize mean & scale ---------------
__global__ void k_psum2() {
    float r[9];
    #pragma unroll
    for (int j = 0; j < 9; j++) r[j] = g_part[threadIdx.x * 9 + j];
    __shared__ float sh[8][9];
    #pragma unroll
    for (int o = 16; o > 0; o >>= 1) {
        r[0] += __shfl_xor_sync(0xffffffffu, r[0], o);
        r[1] += __shfl_xor_sync(0xffffffffu, r[1], o);
        r[2] += __shfl_xor_sync(0xffffffffu, r[2], o);
        r[3] = fminf(r[3], __shfl_xor_sync(0xffffffffu, r[3], o));
        r[4] = fminf(r[4], __shfl_xor_sync(0xffffffffu, r[4], o));
        r[5] = fminf(r[5], __shfl_xor_sync(0xffffffffu, r[5], o));
        r[6] = fmaxf(r[6], __shfl_xor_sync(0xffffffffu, r[6], o));
        r[7] = fmaxf(r[7], __shfl_xor_sync(0xffffffffu, r[7], o));
        r[8] = fmaxf(r[8], __shfl_xor_sync(0xffffffffu, r[8], o));
    }
    int w = threadIdx.x >> 5, l = threadIdx.x & 31;
    if (l == 0)
        #pragma unroll
        for (int j = 0; j < 9; j++) sh[w][j] = r[j];
    __syncthreads();
    if (threadIdx.x == 0) {
        #pragma unroll
        for (int j = 0; j < 9; j++) r[j] = sh[0][j];
        #pragma unroll
        for (int i = 1; i < 8; i++) {
            r[0] += sh[i][0]; r[1] += sh[i][1]; r[2] += sh[i][2];
            r[3] = fminf(r[3], sh[i][3]); r[4] = fminf(r[4], sh[i][4]);
            r[5] = fminf(r[5], sh[i][5]);
            r[6] = fmaxf(r[6], sh[i][6]); r[7] = fmaxf(r[7], sh[i][7]);
            r[8] = fmaxf(r[8], sh[i][8]);
        }
        #pragma unroll
        for (int d = 0; d < 3; d++) {
            float mean = r[d] * (1.0f / NPTS);
            float scl = fmaxf(fmaxf(r[6 + d] - mean, mean - r[3 + d]), 1e-6f);
            g_sum3[d]  = r[d];
            g_scale[d] = scl;
        }
    }
}

// ---------------- K4: LayerNorm, warp per row, float4 in / bf16x4 out -------
__global__ void k_ln(const float* __restrict__ feats,
                     const float* __restrict__ gg, const float* __restrict__ bb) {
    int row = blockIdx.x * 8 + (threadIdx.x >> 5);
    if (row >= NPTS) return;
    int l = threadIdx.x & 31;
    float4 v = reinterpret_cast<const float4*>(feats + (size_t)row * CH)[l];
    float s = v.x + v.y + v.z + v.w;
    #pragma unroll
    for (int o = 16; o > 0; o >>= 1) s += __shfl_xor_sync(0xffffffffu, s, o);
    float mean = s * (1.0f / CH);
    float dx = v.x - mean, dy = v.y - mean, dz = v.z - mean, dw = v.w - mean;
    float q = dx * dx + dy * dy + dz * dz + dw * dw;
    #pragma unroll
    for (int o = 16; o > 0; o >>= 1) q += __shfl_xor_sync(0xffffffffu, q, o);
    float rstd = rsqrtf(q * (1.0f / CH) + 1e-5f);
    float4 g4 = reinterpret_cast<const float4*>(gg)[l];
    float4 b4 = reinterpret_cast<const float4*>(bb)[l];
    __nv_bfloat162 lo, hi;
    lo.x = __float2bfloat16(dx * rstd * g4.x + b4.x);
    lo.y = __float2bfloat16(dy * rstd * g4.y + b4.y);
    hi.x = __float2bfloat16(dz * rstd * g4.z + b4.z);
    hi.y = __float2bfloat16(dw * rstd * g4.w + b4.w);
    uint2 u;
    u.x = *reinterpret_cast<uint32_t*>(&lo);
    u.y = *reinterpret_cast<uint32_t*>(&hi);
    reinterpret_cast<uint2*>(g_xb + (size_t)row * CH)[l] = u;
}

// ---------------- K5: gather, warp per point, no smem/syncthreads -----------
__global__ __launch_bounds__(256)
void k_gather(const float* __restrict__ pts,
              const int* __restrict__ nbr,
              const float* __restrict__ bw1, const float* __restrict__ bb1,
              const float* __restrict__ bw2, const float* __restrict__ bb2) {
    int w = threadIdx.x >> 5, l = threadIdx.x & 31;
    int n = blockIdx.x * 8 + w;
    if (n >= NPTS) return;

    int sidx = 0, vflag = 0;
    if (l < KN) {
        int v = nbr[(size_t)n * KN + l];
        vflag = (v >= 0 && v < NPTS) ? 1 : 0;
        sidx = v < 0 ? 0 : (v >= NPTS ? (NPTS - 1) : v);
    }
    unsigned ball = __ballot_sync(0xffffffffu, vflag);
    float inv = 1.0f / fmaxf((float)__popc(ball), 1.0f);

    // neighbor feature mean (lane covers 4 channels via uint2 of bf16x2)
    const uint2* xb = reinterpret_cast<const uint2*>(g_xb);
    float a0 = 0.f, a1 = 0.f, a2 = 0.f, a3 = 0.f;
    #pragma unroll
    for (int k = 0; k < KN; k++) {
        int idx = __shfl_sync(0xffffffffu, sidx, k);
        float wk = (float)((ball >> k) & 1u);
        uint2 u = xb[(size_t)idx * 32 + l];
        __nv_bfloat162 b0 = *reinterpret_cast<__nv_bfloat162*>(&u.x);
        __nv_bfloat162 b1 = *reinterpret_cast<__nv_bfloat162*>(&u.y);
        a0 += wk * __bfloat162float(b0.x);
        a1 += wk * __bfloat162float(b0.y);
        a2 += wk * __bfloat162float(b1.x);
        a3 += wk * __bfloat162float(b1.y);
    }
    float mf0 = a0 * inv, mf1 = a1 * inv, mf2 = a2 * inv, mf3 = a3 * inv;
    {
        __nv_bfloat162 p0, p1;
        p0.x = __float2bfloat16(mf0); p0.y = __float2bfloat16(mf1);
        p1.x = __float2bfloat16(mf2); p1.y = __float2bfloat16(mf3);
        uint2 u;
        u.x = *reinterpret_cast<uint32_t*>(&p0);
        u.y = *reinterpret_cast<uint32_t*>(&p1);
        reinterpret_cast<uint2*>(g_mfb)[(size_t)n * 32 + l] = u;
    }

    // feat_diff
    uint2 xu = xb[(size_t)n * 32 + l];
    __nv_bfloat162 x0 = *reinterpret_cast<__nv_bfloat162*>(&xu.x);
    __nv_bfloat162 x1 = *reinterpret_cast<__nv_bfloat162*>(&xu.y);
    float d0 = __bfloat162float(x0.x) - mf0;
    float d1 = __bfloat162float(x0.y) - mf1;
    float d2 = __bfloat162float(x1.x) - mf2;
    float d3 = __bfloat162float(x1.y) - mf3;
    float fq = d0 * d0 + d1 * d1 + d2 * d2 + d3 * d3;
    #pragma unroll
    for (int o = 16; o > 0; o >>= 1) fq += __shfl_xor_sync(0xffffffffu, fq, o);
    float fd = sqrtf(fq);

    // neighbor point mean (lane k < 16 handles its own neighbor's coords)
    float px = 0.f, py = 0.f, pz = 0.f;
    if (l < KN && vflag) {
        px = pts[(size_t)sidx * 3 + 0];
        py = pts[(size_t)sidx * 3 + 1];
        pz = pts[(size_t)sidx * 3 + 2];
    }
    #pragma unroll
    for (int o = 16; o > 0; o >>= 1) {
        px += __shfl_xor_sync(0xffffffffu, px, o);
        py += __shfl_xor_sync(0xffffffffu, py, o);
        pz += __shfl_xor_sync(0xffffffffu, pz, o);
    }
    float cx = pts[(size_t)n * 3 + 0] - px * inv;
    float cy = pts[(size_t)n * 3 + 1] - py * inv;
    float cz = pts[(size_t)n * 3 + 2] - pz * inv;
    float cd = sqrtf(cx * cx + cy * cy + cz * cz);

    // boundary MLP (2 -> 128 -> 1), lane covers hidden units l, l+32, l+64, l+96
    float acc = 0.f;
    #pragma unroll
    for (int j = 0; j < 4; j++) {
        int u = l + j * 32;
        float h = gelu_exact(fd * bw1[u] + cd * bw1[CH + u] + bb1[u]);
        acc += h * bw2[u];
    }
    #pragma unroll
    for (int o = 16; o > 0; o >>= 1) acc += __shfl_xor_sync(0xffffffffu, acc, o);
    if (l == 0) g_bnd[n] = sigm(acc + bb2[0]);
}

// ---------------- K_pack: fp32 [128K x 128N] -> mma B-fragment order ---------
__global__ void k_pack(const float* __restrict__ w0, const float* __restrict__ w1,
                       const float* __restrict__ w2, const float* __restrict__ w3,
                       const float* __restrict__ w4, const float* __restrict__ w5,
                       const float* __restrict__ w6, const float* __restrict__ w7,
                       const float* __restrict__ w8) {
    const float* W;
    switch (blockIdx.y) {
        case 0: W = w0; break;  case 1: W = w1; break;  case 2: W = w2; break;
        case 3: W = w3; break;  case 4: W = w4; break;  case 5: W = w5; break;
        case 6: W = w6; break;  case 7: W = w7; break;  default: W = w8; break;
    }
    int idx = blockIdx.x * 256 + threadIdx.x;      // 0..4095
    int lane = idx & 31;
    int kk   = (idx >> 5) & 7;
    int ns   = idx >> 8;
    int g = lane >> 2, tig = lane & 3;
    int n  = ns * 8 + g;
    int k0 = kk * 16 + tig * 2;
    __nv_bfloat162 lo, hi;
    lo.x = __float2bfloat16(W[(size_t)k0 * CH + n]);
    lo.y = __float2bfloat16(W[(size_t)(k0 + 1) * CH + n]);
    hi.x = __float2bfloat16(W[(size_t)(k0 + 8) * CH + n]);
    hi.y = __float2bfloat16(W[(size_t)(k0 + 9) * CH + n]);
    uint2 v;
    v.x = *reinterpret_cast<uint32_t*>(&lo);
    v.y = *reinterpret_cast<uint32_t*>(&hi);
    g_pk[blockIdx.y * 4096 + idx] = v;
}

// ---------------- mma helpers ------------------------------------------------
__device__ __forceinline__ void mma16816(float (&c)[4], const uint32_t (&a)[4],
                                         uint32_t b0, uint32_t b1) {
    asm volatile(
        "mma.sync.aligned.m16n8k16.row.col.f32.bf16.bf16.f32 "
        "{%0,%1,%2,%3}, {%4,%5,%6,%7}, {%8,%9}, {%0,%1,%2,%3};\n"
        : "+f"(c[0]), "+f"(c[1]), "+f"(c[2]), "+f"(c[3])
        : "r"(a[0]), "r"(a[1]), "r"(a[2]), "r"(a[3]), "r"(b0), "r"(b1));
}

__device__ __forceinline__ void ldm4(uint32_t (&r)[4], uint32_t addr) {
    asm volatile("ldmatrix.sync.aligned.m8n8.x4.shared.b16 {%0,%1,%2,%3}, [%4];"
                 : "=r"(r[0]), "=r"(r[1]), "=r"(r[2]), "=r"(r[3]) : "r"(addr));
}

__device__ __forceinline__ void frag_init(float (&c)[4][2][4],
                                          const float* __restrict__ bias,
                                          const float* __restrict__ wb,
                                          const float* bndp,
                                          int warp, int g, int tig) {
    #pragma unroll
    for (int sub = 0; sub < 2; sub++) {
        int nA = warp * 16 + sub * 8 + tig * 2;
        float bA = bias[nA], bB = bias[nA + 1];
        float wA = wb ? wb[nA] : 0.f, wB = wb ? wb[nA + 1] : 0.f;
        #pragma unroll
        for (int mt = 0; mt < 4; mt++) {
            float e0 = bndp ? bndp[mt * 16 + g] : 0.f;
            float e8 = bndp ? bndp[mt * 16 + g + 8] : 0.f;
            c[mt][sub][0] = bA + e0 * wA;
            c[mt][sub][1] = bB + e0 * wB;
            c[mt][sub][2] = bA + e8 * wA;
            c[mt][sub][3] = bB + e8 * wB;
        }
    }
}

// A from smem via ldmatrix.x4; B from fragment-packed global (L2-hot)
__device__ __forceinline__ void gemm_acc(float (&c)[4][2][4], uint32_t abase,
                                         const uint2* __restrict__ pk,
                                         int warp, int lane) {
    int rsel = (lane & 7) + ((lane >> 3) & 1) * 8;
    int csel = (lane >> 4) * 8;
    uint32_t off0 = abase + (uint32_t)((rsel * ASTRIDE + csel) * 2);
    #pragma unroll
    for (int kk = 0; kk < 8; kk++) {
        uint32_t a[4][4];
        #pragma unroll
        for (int mt = 0; mt < 4; mt++)
            ldm4(a[mt], off0 + mt * (16 * ASTRIDE * 2) + kk * 32);
        #pragma unroll
        for (int sub = 0; sub < 2; sub++) {
            uint2 b = pk[((warp * 2 + sub) * 8 + kk) * 32 + lane];
            #pragma unroll
            for (int mt = 0; mt < 4; mt++)
                mma16816(c[mt][sub], a[mt], b.x, b.y);
        }
    }
}

__device__ __forceinline__ void frag_store(__nv_bfloat16 (*D)[ASTRIDE],
                                           const float (&c)[4][2][4], int act,
                                           int warp, int g, int tig) {
    #pragma unroll
    for (int sub = 0; sub < 2; sub++) {
        int nA = warp * 16 + sub * 8 + tig * 2;
        #pragma unroll
        for (int mt = 0; mt < 4; mt++) {
            int r = mt * 16 + g;
            float v0 = c[mt][sub][0], v1 = c[mt][sub][1];
            float v2 = c[mt][sub][2], v3 = c[mt][sub][3];
            if (act) { v0 = gelu_exact(v0); v1 = gelu_exact(v1);
                       v2 = gelu_exact(v2); v3 = gelu_exact(v3); }
            __nv_bfloat162 p01, p23;
            p01.x = __float2bfloat16(v0); p01.y = __float2bfloat16(v1);
            p23.x = __float2bfloat16(v2); p23.y = __float2bfloat16(v3);
            *reinterpret_cast<uint32_t*>(&D[r][nA])     = *reinterpret_cast<uint32_t*>(&p01);
            *reinterpret_cast<uint32_t*>(&D[r + 8][nA]) = *reinterpret_cast<uint32_t*>(&p23);
        }
    }
}

// ---------------- K6: fused MLPs, BP=64, single accumulator set -------------
#define SMEM_ARR (BP * ASTRIDE * 2)          // 17408
#define SMEM_MLP (4 * SMEM_ARR + 256 + 768)  // xs,ms,cs,hs + bnd + cpt = 70656

__global__ __launch_bounds__(256, 2)
void k_mlp(const float* __restrict__ pts, const float* __restrict__ feats,
           const float* __restrict__ cpw1, const float* __restrict__ cpb1,
           const float* __restrict__ cpb2,
           const float* __restrict__ mw1,  const float* __restrict__ mb1,
           const float* __restrict__ mb2,
           const float* __restrict__ gw1,  const float* __restrict__ gb1,
           const float* __restrict__ gb2,
           const float* __restrict__ ob,
           float* __restrict__ out) {
    extern __shared__ char dyn[];
    __nv_bfloat16 (*xs)[ASTRIDE] = reinterpret_cast<__nv_bfloat16(*)[ASTRIDE]>(dyn);
    __nv_bfloat16 (*ms)[ASTRIDE] = reinterpret_cast<__nv_bfloat16(*)[ASTRIDE]>(dyn + SMEM_ARR);
    __nv_bfloat16 (*cs)[ASTRIDE] = reinterpret_cast<__nv_bfloat16(*)[ASTRIDE]>(dyn + 2 * SMEM_ARR);
    __nv_bfloat16 (*hs)[ASTRIDE] = reinterpret_cast<__nv_bfloat16(*)[ASTRIDE]>(dyn + 3 * SMEM_ARR);
    float* bnd       = reinterpret_cast<float*>(dyn + 4 * SMEM_ARR);
    float (*cpt)[3]  = reinterpret_cast<float(*)[3]>(dyn + 4 * SMEM_ARR + 256);

    int t = threadIdx.x;
    int lane = t & 31, warp = t >> 5, g = lane >> 2, tig = lane & 3;
    int p0 = blockIdx.x * BP;

    uint32_t a_xs = (uint32_t)__cvta_generic_to_shared(xs);
    uint32_t a_ms = (uint32_t)__cvta_generic_to_shared(ms);
    uint32_t a_cs = (uint32_t)__cvta_generic_to_shared(cs);
    uint32_t a_hs = (uint32_t)__cvta_generic_to_shared(hs);

    // load x / mf tiles as bf16x2 words (pad rows are zero-initialized globals)
    {
        const uint32_t* xb32 = reinterpret_cast<const uint32_t*>(g_xb);
        const uint32_t* mb32 = reinterpret_cast<const uint32_t*>(g_mfb);
        int pair = t & 63, pr0 = t >> 6;
        #pragma unroll
        for (int p = pr0; p < BP; p += 4) {
            uint32_t vx = xb32[(size_t)(p0 + p) * 64 + pair];
            uint32_t vm = mb32[(size_t)(p0 + p) * 64 + pair];
            *reinterpret_cast<uint32_t*>(&xs[p][pair * 2]) = vx;
            *reinterpret_cast<uint32_t*>(&ms[p][pair * 2]) = vm;
        }
    }
    if (t < BP) bnd[t] = g_bnd[p0 + t];
    if (t < BP * 3) {
        int p = t / 3, d = t - 3 * p;
        int row = min(p0 + p, NPTS - 1);
        float mean = g_sum3[d] * (1.0f / NPTS);
        cpt[p][d] = (pts[(size_t)row * 3 + d] - mean) / g_scale[d];
    }
    __syncthreads();

    // coord-embed hidden (3 -> 128), SIMT
    {
        int col = t & 127, half = t >> 7;
        float w0 = cpw1[col], w1 = cpw1[CH + col], w2 = cpw1[2 * CH + col], b = cpb1[col];
        #pragma unroll
        for (int p = half; p < BP; p += 2)
            hs[p][col] = __float2bfloat16(
                gelu_exact(cpt[p][0] * w0 + cpt[p][1] * w1 + cpt[p][2] * w2 + b));
    }
    __syncthreads();

    float c[4][2][4];

    // 1) coord_embed = coord_hidden @ cp_w2 + cp_b2  -> cs
    frag_init(c, cpb2, nullptr, nullptr, warp, g, tig);
    gemm_acc(c, a_hs, g_pk + 0 * 4096, warp, lane);
    frag_store(cs, c, 0, warp, g, tig);
    __syncthreads();

    // 2) mix hidden: [x | mf | bnd | ce] @ mix_w1 + b -> gelu -> hs
    //    (hs's coord-hidden contents already consumed in pass 1)
    frag_init(c, mb1, mw1 + 256 * CH, bnd, warp, g, tig);
    gemm_acc(c, a_xs, g_pk + 1 * 4096, warp, lane);
    gemm_acc(c, a_ms, g_pk + 2 * 4096, warp, lane);
    gemm_acc(c, a_cs, g_pk + 3 * 4096, warp, lane);
    __syncthreads();                 // everyone done reading hs (pass 1) + cs
    frag_store(hs, c, 1, warp, g, tig);

    // 3) gate hidden: [x | mf | bnd] @ gate_w1 + b -> gelu -> cs (ce dead)
    frag_init(c, gb1, gw1 + 256 * CH, bnd, warp, g, tig);
    gemm_acc(c, a_xs, g_pk + 5 * 4096, warp, lane);
    gemm_acc(c, a_ms, g_pk + 6 * 4096, warp, lane);
    __syncthreads();                 // cs reads (pass 2) done; hs stores visible
    frag_store(cs, c, 1, warp, g, tig);
    __syncthreads();

    // 4) gate = sigmoid(gate_hidden @ gate_w2 + b), packed to bf16x2 regs
    frag_init(c, gb2, nullptr, nullptr, warp, g, tig);
    gemm_acc(c, a_cs, g_pk + 7 * 4096, warp, lane);
    uint32_t ga[4][2][2];
    #pragma unroll
    for (int mt = 0; mt < 4; mt++)
        #pragma unroll
        for (int sub = 0; sub < 2; sub++) {
            __nv_bfloat162 p01, p23;
            p01.x = __float2bfloat16(sigm(c[mt][sub][0]));
            p01.y = __float2bfloat16(sigm(c[mt][sub][1]));
            p23.x = __float2bfloat16(sigm(c[mt][sub][2]));
            p23.y = __float2bfloat16(sigm(c[mt][sub][3]));
            ga[mt][sub][0] = *reinterpret_cast<uint32_t*>(&p01);
            ga[mt][sub][1] = *reinterpret_cast<uint32_t*>(&p23);
        }

    // 5) refined = mix_hidden @ mix_w2 + b;  rs = gate * refined -> xs (dead)
    frag_init(c, mb2, nullptr, nullptr, warp, g, tig);
    gemm_acc(c, a_hs, g_pk + 4 * 4096, warp, lane);
    #pragma unroll
    for (int mt = 0; mt < 4; mt++)
        #pragma unroll
        for (int sub = 0; sub < 2; sub++) {
            __nv_bfloat162 g01 = *reinterpret_cast<__nv_bfloat162*>(&ga[mt][sub][0]);
            __nv_bfloat162 g23 = *reinterpret_cast<__nv_bfloat162*>(&ga[mt][sub][1]);
            c[mt][sub][0] *= __bfloat162float(g01.x);
            c[mt][sub][1] *= __bfloat162float(g01.y);
            c[mt][sub][2] *= __bfloat162float(g23.x);
            c[mt][sub][3] *= __bfloat162float(g23.y);
        }
    __syncthreads();                 // xs reads (pass 3) done
    frag_store(xs, c, 0, warp, g, tig);
    __syncthreads();

    // 6) out = feats + rs @ out_w + out_b
    frag_init(c, ob, nullptr, nullptr, warp, g, tig);
    gemm_acc(c, a_xs, g_pk + 8 * 4096, warp, lane);
    #pragma unroll
    for (int sub = 0; sub < 2; sub++) {
        int nA = warp * 16 + sub * 8 + tig * 2;
        #pragma unroll
        for (int mt = 0; mt < 4; mt++) {
            int r = mt * 16 + g;
            int row0 = p0 + r, row8 = row0 + 8;
            if (row0 < NPTS) {
                size_t o = (size_t)row0 * CH + nA;
                float2 f = *reinterpret_cast<const float2*>(feats + o);
                float2 v; v.x = f.x + c[mt][sub][0]; v.y = f.y + c[mt][sub][1];
                *reinterpret_cast<float2*>(out + o) = v;
            }
            if (row8 < NPTS) {
                size_t o = (size_t)row8 * CH + nA;
                float2 f = *reinterpret_cast<const float2*>(feats + o);
                float2 v; v.x = f.x + c[mt][sub][2]; v.y = f.y + c[mt][sub][3];
                *reinterpret_cast<float2*>(out + o) = v;
            }
        }
    }
}

// ---------------- launch -----------------------------------------------------
extern "C" void kernel_launch(void* const* d_in, const int* in_sizes, int n_in,
                              void* d_out, int out_size) {
    const float* feats = (const float*)d_in[0];
    const float* pts   = (const float*)d_in[1];
    const int*   nbr   = (const int*)d_in[2];     // int64 downcast to int32 by harness
    const float* ln_g  = (const float*)d_in[3];
    const float* ln_b  = (const float*)d_in[4];
    const float* cpw1  = (const float*)d_in[5];
    const float* cpb1  = (const float*)d_in[6];
    const float* cpw2  = (const float*)d_in[7];
    const float* cpb2  = (const float*)d_in[8];
    const float* bw1   = (const float*)d_in[9];
    const float* bb1   = (const float*)d_in[10];
    const float* bw2   = (const float*)d_in[11];
    const float* bb2   = (const float*)d_in[12];
    const float* mw1   = (const float*)d_in[13];
    const float* mb1   = (const float*)d_in[14];
    const float* mw2   = (const float*)d_in[15];
    const float* mb2   = (const float*)d_in[16];
    const float* gw1   = (const float*)d_in[17];
    const float* gb1   = (const float*)d_in[18];
    const float* gw2   = (const float*)d_in[19];
    const float* gb2   = (const float*)d_in[20];
    const float* ow    = (const float*)d_in[21];
    const float* ob    = (const float*)d_in[22];
    float* out = (float*)d_out;

    (void)in_sizes; (void)n_in; (void)out_size;

    cudaFuncSetAttribute(k_mlp, cudaFuncAttributeMaxDynamicSharedMemorySize, SMEM_MLP);

    // order chosen so launch #3 (ncu capture slot) = k_gather
    k_ln<<<(NPTS + 7) / 8, 256>>>(feats, ln_g, ln_b);                    // 0
    k_psum<<<NBLK_RED, 256>>>(pts);                                      // 1
    k_psum2<<<1, NBLK_RED>>>();                                          // 2
    k_gather<<<(NPTS + 7) / 8, 256>>>(pts, nbr, bw1, bb1, bw2, bb2);     // 3
    {
        dim3 grid(16, 9);
        k_pack<<<grid, 256>>>(cpw2,
                              mw1,                 // mix rows   0..127 (x)
                              mw1 + 128 * CH,      // mix rows 128..255 (mf)
                              mw1 + 257 * CH,      // mix rows 257..384 (ce)
                              mw2,
                              gw1,                 // gate rows  0..127 (x)
                              gw1 + 128 * CH,      // gate rows 128..255 (mf)
                              gw2,
                              ow);                                       // 4
    }
    k_mlp<<<NPAD / BP, 256, SMEM_MLP>>>(pts, feats,
                                        cpw1, cpb1, cpb2,
                                        mw1, mb1, mb2,
                                        gw1, gb1, gb2,
                                        ob, out);                        // 5
}

// round 8
// speedup vs baseline: 5.7378x; 1.1457x over previous
#include <cuda_runtime.h>
#include <cuda_bf16.h>
#include <math.h>
#include <stdint.h>

#define NPTS 100000
#define NPAD 100032          // 64-aligned padding (device globals zero-init)
#define CH   128
#define KN   16
#define BP   64              // points per k_mlp block (four m16 tiles)
#define NBLK_RED 256
#define ASTRIDE 136          // bf16 elems per smem row (272B) -> conflict-free

// ---------------- scratch (device globals; no allocations allowed) ----------
__device__ __nv_bfloat16 g_xb [(size_t)NPAD * CH];  // LayerNorm output (bf16)
__device__ __nv_bfloat16 g_mfb[(size_t)NPAD * CH];  // neighbor mean feature (bf16)
__device__ float         g_bnd[NPAD];               // boundary score
__device__ float         g_part[NBLK_RED * 9];      // per-block {sum3,min3,max3}
__device__ uint2         g_pk[9 * 4096];            // fragment-packed bf16 weights

// ---------------- fast math --------------------------------------------------
__device__ __forceinline__ float tanh_fast(float x) {
    float y; asm("tanh.approx.f32 %0, %1;" : "=f"(y) : "f"(x)); return y;
}
__device__ __forceinline__ float gelu_fast(float v) {
    // tanh-form GELU with MUFU.TANH; |err| <~ 1e-3 abs on hidden units
    float t = v * fmaf(v * v, 0.0356774081f, 0.7978845608f);
    return 0.5f * v * (1.0f + tanh_fast(t));
}
__device__ __forceinline__ float sigm(float v) {
    return 1.0f / (1.0f + __expf(-v));
}

// ---------------- K_prep: weight pack (blocks 0..143) + point stats ---------
__global__ void k_prep(const float* __restrict__ pts,
                       const float* __restrict__ w0, const float* __restrict__ w1,
                       const float* __restrict__ w2, const float* __restrict__ w3,
                       const float* __restrict__ w4, const float* __restrict__ w5,
                       const float* __restrict__ w6, const float* __restrict__ w7,
                       const float* __restrict__ w8) {
    if (blockIdx.x < 144) {
        // ---- weight packing: fp32 [128K x 128N] -> mma B-fragment bf16 ----
        int by = blockIdx.x / 16, bx = blockIdx.x % 16;
        const float* W;
        switch (by) {
            case 0: W = w0; break;  case 1: W = w1; break;  case 2: W = w2; break;
            case 3: W = w3; break;  case 4: W = w4; break;  case 5: W = w5; break;
            case 6: W = w6; break;  case 7: W = w7; break;  default: W = w8; break;
        }
        int idx = bx * 256 + threadIdx.x;      // 0..4095
        int lane = idx & 31;
        int kk   = (idx >> 5) & 7;
        int ns   = idx >> 8;
        int g = lane >> 2, tig = lane & 3;
        int n  = ns * 8 + g;
        int k0 = kk * 16 + tig * 2;
        __nv_bfloat162 lo, hi;
        lo.x = __float2bfloat16(W[(size_t)k0 * CH + n]);
        lo.y = __float2bfloat16(W[(size_t)(k0 + 1) * CH + n]);
        hi.x = __float2bfloat16(W[(size_t)(k0 + 8) * CH + n]);
        hi.y = __float2bfloat16(W[(size_t)(k0 + 9) * CH + n]);
        uint2 v;
        v.x = *reinterpret_cast<uint32_t*>(&lo);
        v.y = *reinterpret_cast<uint32_t*>(&hi);
        g_pk[by * 4096 + idx] = v;
        return;
    }
    // ---- point stats partials: per-block {sum, min, max} per dim ----
    int bid = blockIdx.x - 144;   // 0..255
    float s0 = 0.f, s1 = 0.f, s2 = 0.f;
    float mn0 = 1e30f, mn1 = 1e30f, mn2 = 1e30f;
    float mx0 = -1e30f, mx1 = -1e30f, mx2 = -1e30f;
    for (int i = bid * 256 + threadIdx.x; i < NPTS; i += NBLK_RED * 256) {
        float p0 = pts[3 * i + 0], p1 = pts[3 * i + 1], p2 = pts[3 * i + 2];
        s0 += p0; s1 += p1; s2 += p2;
        mn0 = fminf(mn0, p0); mn1 = fminf(mn1, p1); mn2 = fminf(mn2, p2);
        mx0 = fmaxf(mx0, p0); mx1 = fmaxf(mx1, p1); mx2 = fmaxf(mx2, p2);
    }
    __shared__ float sh[8][9];
    #pragma unroll
    for (int o = 16; o > 0; o >>= 1) {
        s0 += __shfl_xor_sync(0xffffffffu, s0, o);
        s1 += __shfl_xor_sync(0xffffffffu, s1, o);
        s2 += __shfl_xor_sync(0xffffffffu, s2, o);
        mn0 = fminf(mn0, __shfl_xor_sync(0xffffffffu, mn0, o));
        mn1 = fminf(mn1, __shfl_xor_sync(0xffffffffu, mn1, o));
        mn2 = fminf(mn2, __shfl_xor_sync(0xffffffffu, mn2, o));
        mx0 = fmaxf(mx0, __shfl_xor_sync(0xffffffffu, mx0, o));
        mx1 = fmaxf(mx1, __shfl_xor_sync(0xffffffffu, mx1, o));
        mx2 = fmaxf(mx2, __shfl_xor_sync(0xffffffffu, mx2, o));
    }
    int w = threadIdx.x >> 5, l = threadIdx.x & 31;
    if (l == 0) {
        sh[w][0] = s0;  sh[w][1] = s1;  sh[w][2] = s2;
        sh[w][3] = mn0; sh[w][4] = mn1; sh[w][5] = mn2;
        sh[w][6] = mx0; sh[w][7] = mx1; sh[w][8] = mx2;
    }
    __syncthreads();
    if (threadIdx.x == 0) {
        float r[9];
        #pragma unroll
        for (int j = 0; j < 9; j++) r[j] = sh[0][j];
        #pragma unroll
        for (int i = 1; i < 8; i++) {
            r[0] += sh[i][0]; r[1] += sh[i][1]; r[2] += sh[i][2];
            r[3] = fminf(r[3], sh[i][3]); r[4] = fminf(r[4], sh[i][4]);
            r[5] = fminf(r[5], sh[i][5]);
            r[6] = fmaxf(r[6], sh[i][6]); r[7] = fmaxf(r[7], sh[i][7]);
            r[8] = fmaxf(r[8], sh[i][8]);
        }
        #pragma unroll
        for (int j = 0; j < 9; j++) g_part[bid * 9 + j] = r[j];
    }
}

// ---------------- K_ln: LayerNorm, warp per row, float4 in / bf16x4 out -----
__global__ void k_ln(const float* __restrict__ feats,
                     const float* __restrict__ gg, const float* __restrict__ bb) {
    int row = blockIdx.x * 8 + (threadIdx.x >> 5);
    if (row >= NPTS) return;
    int l = threadIdx.x & 31;
    float4 v = reinterpret_cast<const float4*>(feats + (size_t)row * CH)[l];
    float s = v.x + v.y + v.z + v.w;
    #pragma unroll
    for (int o = 16; o > 0; o >>= 1) s += __shfl_xor_sync(0xffffffffu, s, o);
    float mean = s * (1.0f / CH);
    float dx = v.x - mean, dy = v.y - mean, dz = v.z - mean, dw = v.w - mean;
    float q = dx * dx + dy * dy + dz * dz + dw * dw;
    #pragma unroll
    for (int o = 16; o > 0; o >>= 1) q += __shfl_xor_sync(0xffffffffu, q, o);
    float rstd = rsqrtf(q * (1.0f / CH) + 1e-5f);
    float4 g4 = reinterpret_cast<const float4*>(gg)[l];
    float4 b4 = reinterpret_cast<const float4*>(bb)[l];
    __nv_bfloat162 lo, hi;
    lo.x = __float2bfloat16(dx * rstd * g4.x + b4.x);
    lo.y = __float2bfloat16(dy * rstd * g4.y + b4.y);
    hi.x = __float2bfloat16(dz * rstd * g4.z + b4.z);
    hi.y = __float2bfloat16(dw * rstd * g4.w + b4.w);
    uint2 u;
    u.x = *reinterpret_cast<uint32_t*>(&lo);
    u.y = *reinterpret_cast<uint32_t*>(&hi);
    reinterpret_cast<uint2*>(g_xb + (size_t)row * CH)[l] = u;
}

// ---------------- K_gather: warp per point, f32x2 packed accumulate ---------
__global__ __launch_bounds__(256)
void k_gather(const float* __restrict__ pts,
              const int* __restrict__ nbr,
              const float* __restrict__ bw1, const float* __restrict__ bb1,
              const float* __restrict__ bw2, const float* __restrict__ bb2) {
    int w = threadIdx.x >> 5, l = threadIdx.x & 31;
    int n = blockIdx.x * 8 + w;
    if (n >= NPTS) return;

    int sidx = 0, vflag = 0;
    if (l < KN) {
        int v = nbr[(size_t)n * KN + l];
        vflag = (v >= 0 && v < NPTS) ? 1 : 0;
        sidx = v < 0 ? 0 : (v >= NPTS ? (NPTS - 1) : v);
    }
    unsigned ball = __ballot_sync(0xffffffffu, vflag);
    float inv = 1.0f / fmaxf((float)__popc(ball), 1.0f);

    // neighbor feature mean: packed f32x2 FMA, bf16->f32 via shift/mask
    const uint2* xb = reinterpret_cast<const uint2*>(g_xb);
    unsigned long long acc01 = 0ull, acc23 = 0ull;   // {0.f,0.f}
    #pragma unroll
    for (int k = 0; k < KN; k++) {
        int idx = __shfl_sync(0xffffffffu, sidx, k);
        float wk = ((ball >> k) & 1u) ? 1.0f : 0.0f;
        unsigned long long wk2;
        asm("mov.b64 %0, {%1,%1};" : "=l"(wk2) : "f"(wk));
        uint2 u = xb[(size_t)idx * 32 + l];
        uint32_t f0 = u.x << 16, f1 = u.x & 0xffff0000u;
        uint32_t f2 = u.y << 16, f3 = u.y & 0xffff0000u;
        unsigned long long v01, v23;
        asm("mov.b64 %0, {%1,%2};" : "=l"(v01) : "r"(f0), "r"(f1));
        asm("mov.b64 %0, {%1,%2};" : "=l"(v23) : "r"(f2), "r"(f3));
        asm("fma.rn.f32x2 %0, %1, %2, %0;" : "+l"(acc01) : "l"(v01), "l"(wk2));
        asm("fma.rn.f32x2 %0, %1, %2, %0;" : "+l"(acc23) : "l"(v23), "l"(wk2));
    }
    float a0, a1, a2, a3;
    asm("mov.b64 {%0,%1}, %2;" : "=f"(a0), "=f"(a1) : "l"(acc01));
    asm("mov.b64 {%0,%1}, %2;" : "=f"(a2), "=f"(a3) : "l"(acc23));
    float mf0 = a0 * inv, mf1 = a1 * inv, mf2 = a2 * inv, mf3 = a3 * inv;
    {
        __nv_bfloat162 p0, p1;
        p0.x = __float2bfloat16(mf0); p0.y = __float2bfloat16(mf1);
        p1.x = __float2bfloat16(mf2); p1.y = __float2bfloat16(mf3);
        uint2 u;
        u.x = *reinterpret_cast<uint32_t*>(&p0);
        u.y = *reinterpret_cast<uint32_t*>(&p1);
        reinterpret_cast<uint2*>(g_mfb)[(size_t)n * 32 + l] = u;
    }

    // feat_diff
    uint2 xu = xb[(size_t)n * 32 + l];
    float x0 = __uint_as_float(xu.x << 16);
    float x1 = __uint_as_float(xu.x & 0xffff0000u);
    float x2 = __uint_as_float(xu.y << 16);
    float x3 = __uint_as_float(xu.y & 0xffff0000u);
    float d0 = x0 - mf0, d1 = x1 - mf1, d2 = x2 - mf2, d3 = x3 - mf3;
    float fq = d0 * d0 + d1 * d1 + d2 * d2 + d3 * d3;
    #pragma unroll
    for (int o = 16; o > 0; o >>= 1) fq += __shfl_xor_sync(0xffffffffu, fq, o);
    float fd = sqrtf(fq);

    // neighbor point mean (lane k < 16 handles its own neighbor's coords)
    float px = 0.f, py = 0.f, pz = 0.f;
    if (l < KN && vflag) {
        px = pts[(size_t)sidx * 3 + 0];
        py = pts[(size_t)sidx * 3 + 1];
        pz = pts[(size_t)sidx * 3 + 2];
    }
    #pragma unroll
    for (int o = 16; o > 0; o >>= 1) {
        px += __shfl_xor_sync(0xffffffffu, px, o);
        py += __shfl_xor_sync(0xffffffffu, py, o);
        pz += __shfl_xor_sync(0xffffffffu, pz, o);
    }
    float cx = pts[(size_t)n * 3 + 0] - px * inv;
    float cy = pts[(size_t)n * 3 + 1] - py * inv;
    float cz = pts[(size_t)n * 3 + 2] - pz * inv;
    float cd = sqrtf(cx * cx + cy * cy + cz * cz);

    // boundary MLP (2 -> 128 -> 1), lane covers hidden units l, l+32, l+64, l+96
    float acc = 0.f;
    #pragma unroll
    for (int j = 0; j < 4; j++) {
        int u = l + j * 32;
        float h = gelu_fast(fd * bw1[u] + cd * bw1[CH + u] + bb1[u]);
        acc += h * bw2[u];
    }
    #pragma unroll
    for (int o = 16; o > 0; o >>= 1) acc += __shfl_xor_sync(0xffffffffu, acc, o);
    if (l == 0) g_bnd[n] = sigm(acc + bb2[0]);
}

// ---------------- mma helpers ------------------------------------------------
__device__ __forceinline__ void mma16816(float (&c)[4], const uint32_t (&a)[4],
                                         uint32_t b0, uint32_t b1) {
    asm volatile(
        "mma.sync.aligned.m16n8k16.row.col.f32.bf16.bf16.f32 "
        "{%0,%1,%2,%3}, {%4,%5,%6,%7}, {%8,%9}, {%0,%1,%2,%3};\n"
        : "+f"(c[0]), "+f"(c[1]), "+f"(c[2]), "+f"(c[3])
        : "r"(a[0]), "r"(a[1]), "r"(a[2]), "r"(a[3]), "r"(b0), "r"(b1));
}

__device__ __forceinline__ void ldm4(uint32_t (&r)[4], uint32_t addr) {
    asm volatile("ldmatrix.sync.aligned.m8n8.x4.shared.b16 {%0,%1,%2,%3}, [%4];"
                 : "=r"(r[0]), "=r"(r[1]), "=r"(r[2]), "=r"(r[3]) : "r"(addr));
}

__device__ __forceinline__ void frag_init(float (&c)[4][2][4],
                                          const float* __restrict__ bias,
                                          const float* __restrict__ wb,
                                          const float* bndp,
                                          int warp, int g, int tig) {
    #pragma unroll
    for (int sub = 0; sub < 2; sub++) {
        int nA = warp * 16 + sub * 8 + tig * 2;
        float bA = bias[nA], bB = bias[nA + 1];
        float wA = wb ? wb[nA] : 0.f, wB = wb ? wb[nA + 1] : 0.f;
        #pragma unroll
        for (int mt = 0; mt < 4; mt++) {
            float e0 = bndp ? bndp[mt * 16 + g] : 0.f;
            float e8 = bndp ? bndp[mt * 16 + g + 8] : 0.f;
            c[mt][sub][0] = bA + e0 * wA;
            c[mt][sub][1] = bB + e0 * wB;
            c[mt][sub][2] = bA + e8 * wA;
            c[mt][sub][3] = bB + e8 * wB;
        }
    }
}

// A from smem via ldmatrix.x4; B from fragment-packed global (L2-hot)
__device__ __forceinline__ void gemm_acc(float (&c)[4][2][4], uint32_t abase,
                                         const uint2* __restrict__ pk,
                                         int warp, int lane) {
    int rsel = (lane & 7) + ((lane >> 3) & 1) * 8;
    int csel = (lane >> 4) * 8;
    uint32_t off0 = abase + (uint32_t)((rsel * ASTRIDE + csel) * 2);
    #pragma unroll
    for (int kk = 0; kk < 8; kk++) {
        uint32_t a[4][4];
        #pragma unroll
        for (int mt = 0; mt < 4; mt++)
            ldm4(a[mt], off0 + mt * (16 * ASTRIDE * 2) + kk * 32);
        #pragma unroll
        for (int sub = 0; sub < 2; sub++) {
            uint2 b = pk[((warp * 2 + sub) * 8 + kk) * 32 + lane];
            #pragma unroll
            for (int mt = 0; mt < 4; mt++)
                mma16816(c[mt][sub], a[mt], b.x, b.y);
        }
    }
}

__device__ __forceinline__ void frag_store(__nv_bfloat16 (*D)[ASTRIDE],
                                           const float (&c)[4][2][4], int act,
                                           int warp, int g, int tig) {
    #pragma unroll
    for (int sub = 0; sub < 2; sub++) {
        int nA = warp * 16 + sub * 8 + tig * 2;
        #pragma unroll
        for (int mt = 0; mt < 4; mt++) {
            int r = mt * 16 + g;
            float v0 = c[mt][sub][0], v1 = c[mt][sub][1];
            float v2 = c[mt][sub][2], v3 = c[mt][sub][3];
            if (act) { v0 = gelu_fast(v0); v1 = gelu_fast(v1);
                       v2 = gelu_fast(v2); v3 = gelu_fast(v3); }
            __nv_bfloat162 p01, p23;
            p01.x = __float2bfloat16(v0); p01.y = __float2bfloat16(v1);
            p23.x = __float2bfloat16(v2); p23.y = __float2bfloat16(v3);
            *reinterpret_cast<uint32_t*>(&D[r][nA])     = *reinterpret_cast<uint32_t*>(&p01);
            *reinterpret_cast<uint32_t*>(&D[r + 8][nA]) = *reinterpret_cast<uint32_t*>(&p23);
        }
    }
}

// ---------------- K_mlp: fused MLPs, BP=64, single accumulator set ----------
#define SMEM_ARR (BP * ASTRIDE * 2)          // 17408
#define SMEM_MLP (4 * SMEM_ARR + 256 + 768)  // xs,ms,cs,hs + bnd + cpt = 70656

__global__ __launch_bounds__(256, 2)
void k_mlp(const float* __restrict__ pts, const float* __restrict__ feats,
           const float* __restrict__ cpw1, const float* __restrict__ cpb1,
           const float* __restrict__ cpb2,
           const float* __restrict__ mw1,  const float* __restrict__ mb1,
           const float* __restrict__ mb2,
           const float* __restrict__ gw1,  const float* __restrict__ gb1,
           const float* __restrict__ gb2,
           const float* __restrict__ ob,
           float* __restrict__ out) {
    extern __shared__ char dyn[];
    __nv_bfloat16 (*xs)[ASTRIDE] = reinterpret_cast<__nv_bfloat16(*)[ASTRIDE]>(dyn);
    __nv_bfloat16 (*ms)[ASTRIDE] = reinterpret_cast<__nv_bfloat16(*)[ASTRIDE]>(dyn + SMEM_ARR);
    __nv_bfloat16 (*cs)[ASTRIDE] = reinterpret_cast<__nv_bfloat16(*)[ASTRIDE]>(dyn + 2 * SMEM_ARR);
    __nv_bfloat16 (*hs)[ASTRIDE] = reinterpret_cast<__nv_bfloat16(*)[ASTRIDE]>(dyn + 3 * SMEM_ARR);
    float* bnd       = reinterpret_cast<float*>(dyn + 4 * SMEM_ARR);
    float (*cpt)[3]  = reinterpret_cast<float(*)[3]>(dyn + 4 * SMEM_ARR + 256);
    __shared__ float sh2[8][9];
    __shared__ float s_mean[3], s_scl[3];

    int t = threadIdx.x;
    int lane = t & 31, warp = t >> 5, g = lane >> 2, tig = lane & 3;
    int p0 = blockIdx.x * BP;

    uint32_t a_xs = (uint32_t)__cvta_generic_to_shared(xs);
    uint32_t a_ms = (uint32_t)__cvta_generic_to_shared(ms);
    uint32_t a_cs = (uint32_t)__cvta_generic_to_shared(cs);
    uint32_t a_hs = (uint32_t)__cvta_generic_to_shared(hs);

    // load x / mf tiles as bf16x2 words (pad rows are zero-initialized globals)
    {
        const uint32_t* xb32 = reinterpret_cast<const uint32_t*>(g_xb);
        const uint32_t* mb32 = reinterpret_cast<const uint32_t*>(g_mfb);
        int pair = t & 63, pr0 = t >> 6;
        #pragma unroll
        for (int p = pr0; p < BP; p += 4) {
            uint32_t vx = xb32[(size_t)(p0 + p) * 64 + pair];
            uint32_t vm = mb32[(size_t)(p0 + p) * 64 + pair];
            *reinterpret_cast<uint32_t*>(&xs[p][pair * 2]) = vx;
            *reinterpret_cast<uint32_t*>(&ms[p][pair * 2]) = vm;
        }
    }
    if (t < BP) bnd[t] = g_bnd[p0 + t];

    // combine point-stat partials (replaces separate psum2 kernel; L2-hot)
    {
        float r[9];
        #pragma unroll
        for (int j = 0; j < 9; j++) r[j] = g_part[t * 9 + j];
        #pragma unroll
        for (int o = 16; o > 0; o >>= 1) {
            r[0] += __shfl_xor_sync(0xffffffffu, r[0], o);
            r[1] += __shfl_xor_sync(0xffffffffu, r[1], o);
            r[2] += __shfl_xor_sync(0xffffffffu, r[2], o);
            r[3] = fminf(r[3], __shfl_xor_sync(0xffffffffu, r[3], o));
            r[4] = fminf(r[4], __shfl_xor_sync(0xffffffffu, r[4], o));
            r[5] = fminf(r[5], __shfl_xor_sync(0xffffffffu, r[5], o));
            r[6] = fmaxf(r[6], __shfl_xor_sync(0xffffffffu, r[6], o));
            r[7] = fmaxf(r[7], __shfl_xor_sync(0xffffffffu, r[7], o));
            r[8] = fmaxf(r[8], __shfl_xor_sync(0xffffffffu, r[8], o));
        }
        if (lane == 0)
            #pragma unroll
            for (int j = 0; j < 9; j++) sh2[warp][j] = r[j];
        __syncthreads();
        if (t == 0) {
            #pragma unroll
            for (int j = 0; j < 9; j++) r[j] = sh2[0][j];
            #pragma unroll
            for (int i = 1; i < 8; i++) {
                r[0] += sh2[i][0]; r[1] += sh2[i][1]; r[2] += sh2[i][2];
                r[3] = fminf(r[3], sh2[i][3]); r[4] = fminf(r[4], sh2[i][4]);
                r[5] = fminf(r[5], sh2[i][5]);
                r[6] = fmaxf(r[6], sh2[i][6]); r[7] = fmaxf(r[7], sh2[i][7]);
                r[8] = fmaxf(r[8], sh2[i][8]);
            }
            #pragma unroll
            for (int d = 0; d < 3; d++) {
                float mean = r[d] * (1.0f / NPTS);
                s_mean[d] = mean;
                s_scl[d]  = fmaxf(fmaxf(r[6 + d] - mean, mean - r[3 + d]), 1e-6f);
            }
        }
        __syncthreads();
    }

    if (t < BP * 3) {
        int p = t / 3, d = t - 3 * p;
        int row = min(p0 + p, NPTS - 1);
        cpt[p][d] = (pts[(size_t)row * 3 + d] - s_mean[d]) / s_scl[d];
    }
    __syncthreads();

    // coord-embed hidden (3 -> 128), SIMT
    {
        int col = t & 127, half = t >> 7;
        float w0 = cpw1[col], w1 = cpw1[CH + col], w2 = cpw1[2 * CH + col], b = cpb1[col];
        #pragma unroll
        for (int p = half; p < BP; p += 2)
            hs[p][col] = __float2bfloat16(
                gelu_fast(cpt[p][0] * w0 + cpt[p][1] * w1 + cpt[p][2] * w2 + b));
    }
    __syncthreads();

    float c[4][2][4];

    // 1) coord_embed = coord_hidden @ cp_w2 + cp_b2  -> cs
    frag_init(c, cpb2, nullptr, nullptr, warp, g, tig);
    gemm_acc(c, a_hs, g_pk + 0 * 4096, warp, lane);
    frag_store(cs, c, 0, warp, g, tig);
    __syncthreads();

    // 2) mix hidden: [x | mf | bnd | ce] @ mix_w1 + b -> gelu -> hs
    frag_init(c, mb1, mw1 + 256 * CH, bnd, warp, g, tig);
    gemm_acc(c, a_xs, g_pk + 1 * 4096, warp, lane);
    gemm_acc(c, a_ms, g_pk + 2 * 4096, warp, lane);
    gemm_acc(c, a_cs, g_pk + 3 * 4096, warp, lane);
    __syncthreads();                 // everyone done reading hs (pass 1) + cs
    frag_store(hs, c, 1, warp, g, tig);

    // 3) gate hidden: [x | mf | bnd] @ gate_w1 + b -> gelu -> cs (ce dead)
    frag_init(c, gb1, gw1 + 256 * CH, bnd, warp, g, tig);
    gemm_acc(c, a_xs, g_pk + 5 * 4096, warp, lane);
    gemm_acc(c, a_ms, g_pk + 6 * 4096, warp, lane);
    __syncthreads();                 // cs reads (pass 2) done; hs stores visible
    frag_store(cs, c, 1, warp, g, tig);
    __syncthreads();

    // 4) gate = sigmoid(gate_hidden @ gate_w2 + b), packed to bf16x2 regs
    frag_init(c, gb2, nullptr, nullptr, warp, g, tig);
    gemm_acc(c, a_cs, g_pk + 7 * 4096, warp, lane);
    uint32_t ga[4][2][2];
    #pragma unroll
    for (int mt = 0; mt < 4; mt++)
        #pragma unroll
        for (int sub = 0; sub < 2; sub++) {
            __nv_bfloat162 p01, p23;
            p01.x = __float2bfloat16(sigm(c[mt][sub][0]));
            p01.y = __float2bfloat16(sigm(c[mt][sub][1]));
            p23.x = __float2bfloat16(sigm(c[mt][sub][2]));
            p23.y = __float2bfloat16(sigm(c[mt][sub][3]));
            ga[mt][sub][0] = *reinterpret_cast<uint32_t*>(&p01);
            ga[mt][sub][1] = *reinterpret_cast<uint32_t*>(&p23);
        }

    // 5) refined = mix_hidden @ mix_w2 + b;  rs = gate * refined -> xs (dead)
    frag_init(c, mb2, nullptr, nullptr, warp, g, tig);
    gemm_acc(c, a_hs, g_pk + 4 * 4096, warp, lane);
    #pragma unroll
    for (int mt = 0; mt < 4; mt++)
        #pragma unroll
        for (int sub = 0; sub < 2; sub++) {
            __nv_bfloat162 g01 = *reinterpret_cast<__nv_bfloat162*>(&ga[mt][sub][0]);
            __nv_bfloat162 g23 = *reinterpret_cast<__nv_bfloat162*>(&ga[mt][sub][1]);
            c[mt][sub][0] *= __bfloat162float(g01.x);
            c[mt][sub][1] *= __bfloat162float(g01.y);
            c[mt][sub][2] *= __bfloat162float(g23.x);
            c[mt][sub][3] *= __bfloat162float(g23.y);
        }
    __syncthreads();                 // xs reads (pass 3) done
    frag_store(xs, c, 0, warp, g, tig);
    __syncthreads();

    // 6) out = feats + rs @ out_w + out_b
    frag_init(c, ob, nullptr, nullptr, warp, g, tig);
    gemm_acc(c, a_xs, g_pk + 8 * 4096, warp, lane);
    #pragma unroll
    for (int sub = 0; sub < 2; sub++) {
        int nA = warp * 16 + sub * 8 + tig * 2;
        #pragma unroll
        for (int mt = 0; mt < 4; mt++) {
            int r = mt * 16 + g;
            int row0 = p0 + r, row8 = row0 + 8;
            if (row0 < NPTS) {
                size_t o = (size_t)row0 * CH + nA;
                float2 f = *reinterpret_cast<const float2*>(feats + o);
                float2 v; v.x = f.x + c[mt][sub][0]; v.y = f.y + c[mt][sub][1];
                *reinterpret_cast<float2*>(out + o) = v;
            }
            if (row8 < NPTS) {
                size_t o = (size_t)row8 * CH + nA;
                float2 f = *reinterpret_cast<const float2*>(feats + o);
                float2 v; v.x = f.x + c[mt][sub][2]; v.y = f.y + c[mt][sub][3];
                *reinterpret_cast<float2*>(out + o) = v;
            }
        }
    }
}

// ---------------- launch -----------------------------------------------------
extern "C" void kernel_launch(void* const* d_in, const int* in_sizes, int n_in,
                              void* d_out, int out_size) {
    const float* feats = (const float*)d_in[0];
    const float* pts   = (const float*)d_in[1];
    const int*   nbr   = (const int*)d_in[2];     // int64 downcast to int32 by harness
    const float* ln_g  = (const float*)d_in[3];
    const float* ln_b  = (const float*)d_in[4];
    const float* cpw1  = (const float*)d_in[5];
    const float* cpb1  = (const float*)d_in[6];
    const float* cpw2  = (const float*)d_in[7];
    const float* cpb2  = (const float*)d_in[8];
    const float* bw1   = (const float*)d_in[9];
    const float* bb1   = (const float*)d_in[10];
    const float* bw2   = (const float*)d_in[11];
    const float* bb2   = (const float*)d_in[12];
    const float* mw1   = (const float*)d_in[13];
    const float* mb1   = (const float*)d_in[14];
    const float* mw2   = (const float*)d_in[15];
    const float* mb2   = (const float*)d_in[16];
    const float* gw1   = (const float*)d_in[17];
    const float* gb1   = (const float*)d_in[18];
    const float* gw2   = (const float*)d_in[19];
    const float* gb2   = (const float*)d_in[20];
    const float* ow    = (const float*)d_in[21];
    const float* ob    = (const float*)d_in[22];
    float* out = (float*)d_out;

    (void)in_sizes; (void)n_in; (void)out_size;

    cudaFuncSetAttribute(k_mlp, cudaFuncAttributeMaxDynamicSharedMemorySize, SMEM_MLP);

    // 4 launches; index 3 (ncu capture slot) = k_mlp
    k_prep<<<144 + NBLK_RED, 256>>>(pts,
                                    cpw2,
                                    mw1,                 // mix rows   0..127 (x)
                                    mw1 + 128 * CH,      // mix rows 128..255 (mf)
                                    mw1 + 257 * CH,      // mix rows 257..384 (ce)
                                    mw2,
                                    gw1,                 // gate rows  0..127 (x)
                                    gw1 + 128 * CH,      // gate rows 128..255 (mf)
                                    gw2,
                                    ow);                                 // 0
    k_ln<<<(NPTS + 7) / 8, 256>>>(feats, ln_g, ln_b);                    // 1
    k_gather<<<(NPTS + 7) / 8, 256>>>(pts, nbr, bw1, bb1, bw2, bb2);     // 2
    k_mlp<<<NPAD / BP, 256, SMEM_MLP>>>(pts, feats,
                                        cpw1, cpb1, cpb2,
                                        mw1, mb1, mb2,
                                        gw1, gb1, gb2,
                                        ob, out);                        // 3
}